// round 8
// baseline (speedup 1.0000x reference)
#include <cuda_runtime.h>
#include <cuda_bf16.h>
#include <math.h>
#include <stdint.h>

#define S_SEG 256
#define WSTRIDE 68     // uint2 stride for packed [rows x 64-pair] tiles
#define TROWS 256      // rows per CTA tile
#define NTHREADS 1024  // 32 warps: (wm 0..7) x (wn 0..3), warp tile 32x32

// ---- global scratch (no allocs allowed) ----
__device__ uint2 g_lW1p[128 * WSTRIDE];
__device__ uint2 g_lW2p[128 * WSTRIDE];
__device__ uint2 g_gW1p[128 * WSTRIDE];
__device__ uint2 g_gW2p[128 * WSTRIDE];
__device__ float g_psum[S_SEG * 128];
__device__ float g_cnt[S_SEG];
__device__ float g_pooled[S_SEG * 128];

struct SmemT {
    uint2 Ap[TROWS * WSTRIDE];  // X packed -> H packed -> float Y[TROWS*136]
    uint2 Wp[128 * WSTRIDE];    // W1 packed, then reloaded with W2 packed
    float b1[128];
    float b2[128];
    int   seg[TROWS];
};  // 139264 + 69632 + 512 + 512 + 1024 = 210944 B -> 1 CTA/SM, 32 warps

__device__ __forceinline__ void split2(float a, float b, uint32_t& hi, uint32_t& lo) {
    __nv_bfloat16 ah = __float2bfloat16(a);
    __nv_bfloat16 bh = __float2bfloat16(b);
    __nv_bfloat16 al = __float2bfloat16(a - __bfloat162float(ah));
    __nv_bfloat16 bl = __float2bfloat16(b - __bfloat162float(bh));
    hi = ((uint32_t)__bfloat16_as_ushort(bh) << 16) | (uint32_t)__bfloat16_as_ushort(ah);
    lo = ((uint32_t)__bfloat16_as_ushort(bl) << 16) | (uint32_t)__bfloat16_as_ushort(al);
}

#define MMA_BF16(d, a0, a1, a2, a3, b0v, b1v)                                 \
    asm volatile(                                                             \
        "mma.sync.aligned.m16n8k16.row.col.f32.bf16.bf16.f32 "                \
        "{%0,%1,%2,%3}, {%4,%5,%6,%7}, {%8,%9}, {%0,%1,%2,%3};"               \
        : "+f"((d)[0]), "+f"((d)[1]), "+f"((d)[2]), "+f"((d)[3])              \
        : "r"(a0), "r"(a1), "r"(a2), "r"(a3), "r"(b0v), "r"(b1v))

// ---------------------------------------------------------------------------
__global__ void prep_kernel(const float* __restrict__ lW1, const float* __restrict__ lW2,
                            const float* __restrict__ gW1, const float* __restrict__ gW2) {
    int tid = blockIdx.x * blockDim.x + threadIdx.x;     // 0..32767
    if (tid < S_SEG * 128) g_psum[tid] = 0.f;
    if (tid < S_SEG)       g_cnt[tid]  = 0.f;
    int m   = tid >> 13;
    int idx = tid & 8191;
    int n   = idx & 127;
    int kp  = idx >> 7;
    const float* src = (m == 0) ? lW1 : (m == 1) ? lW2 : (m == 2) ? gW1 : gW2;
    uint2*       dst = (m == 0) ? g_lW1p : (m == 1) ? g_lW2p : (m == 2) ? g_gW1p : g_gW2p;
    float a = src[(2 * kp) * 128 + n];
    float b = src[(2 * kp + 1) * 128 + n];
    uint32_t hi, lo;
    split2(a, b, hi, lo);
    dst[n * WSTRIDE + kp] = make_uint2(hi, lo);
}

__global__ void finalize_kernel() {
    int i = blockIdx.x * blockDim.x + threadIdx.x;
    if (i < S_SEG * 128)
        g_pooled[i] = g_psum[i] / fmaxf(g_cnt[i >> 7], 1.f);
}

// ---------------------------------------------------------------------------
// fused 2-layer MLP on a 256-row tile. 32 warps: (wm 0..7) x (wn 0..3),
// warp tile 32x32. GAMMA=1: run-length segment-sum. GAMMA=0: tanh(+pooled).
// ---------------------------------------------------------------------------
template <int GAMMA>
__global__ void __launch_bounds__(NTHREADS, 1)
mlp_kernel(const float* __restrict__ x, const int* __restrict__ seg,
           const float* __restrict__ b1g, const float* __restrict__ b2g,
           float* __restrict__ out, int nrows) {
    extern __shared__ char smem_raw[];
    SmemT& sm = *reinterpret_cast<SmemT*>(smem_raw);

    const uint2* __restrict__ W1g = GAMMA ? g_gW1p : g_lW1p;
    const uint2* __restrict__ W2g = GAMMA ? g_gW2p : g_lW2p;

    const int tid   = threadIdx.x;
    const int tile0 = blockIdx.x * TROWS;

    // ---- X tile: load + hi/lo split ----
    for (int i = tid; i < TROWS * 32; i += NTHREADS) {
        int r  = i >> 5;
        int c4 = (i & 31) * 4;
        float4 v = make_float4(0.f, 0.f, 0.f, 0.f);
        if (tile0 + r < nrows)
            v = *reinterpret_cast<const float4*>(x + (size_t)(tile0 + r) * 128 + c4);
        uint32_t h0, l0, h1, l1;
        split2(v.x, v.y, h0, l0);
        split2(v.z, v.w, h1, l1);
        *reinterpret_cast<uint4*>(&sm.Ap[r * WSTRIDE + (c4 >> 1)]) = make_uint4(h0, l0, h1, l1);
    }
    {   // W1 packed -> smem (linear copy)
        const uint4* s1 = reinterpret_cast<const uint4*>(W1g);
        uint4* d1 = reinterpret_cast<uint4*>(sm.Wp);
        for (int i = tid; i < 128 * WSTRIDE / 2; i += NTHREADS) d1[i] = s1[i];
    }
    if (tid < 128) {
        sm.b1[tid] = b1g[tid];
        sm.b2[tid] = b2g[tid];
    }
    if (tid < TROWS)
        sm.seg[tid] = (tile0 + tid < nrows) ? seg[tile0 + tid] : -1;
    __syncthreads();

    const int lane = tid & 31, warp = tid >> 5;
    const int g = lane >> 2, t = lane & 3;
    const int wm = warp >> 2, wn = warp & 3;   // 8 x 4 warp grid
    const int rbase = wm * 32;

    // ================= stage 1: H = relu(X@W1 + b1) =================
    float acc[2][4][4];
#pragma unroll
    for (int a = 0; a < 2; ++a)
#pragma unroll
        for (int b = 0; b < 4; ++b)
#pragma unroll
            for (int c = 0; c < 4; ++c) acc[a][b][c] = 0.f;

#pragma unroll
    for (int ks = 0; ks < 8; ++ks) {
        const int kp0 = ks * 8 + t;
        uint32_t Ah[2][4], Al[2][4];
#pragma unroll
        for (int mt = 0; mt < 2; ++mt) {
            int r0 = rbase + mt * 16 + g;
            uint2 q0 = sm.Ap[r0 * WSTRIDE + kp0];
            uint2 q1 = sm.Ap[(r0 + 8) * WSTRIDE + kp0];
            uint2 q2 = sm.Ap[r0 * WSTRIDE + kp0 + 4];
            uint2 q3 = sm.Ap[(r0 + 8) * WSTRIDE + kp0 + 4];
            Ah[mt][0] = q0.x; Al[mt][0] = q0.y;
            Ah[mt][1] = q1.x; Al[mt][1] = q1.y;
            Ah[mt][2] = q2.x; Al[mt][2] = q2.y;
            Ah[mt][3] = q3.x; Al[mt][3] = q3.y;
        }
#pragma unroll
        for (int nt = 0; nt < 4; ++nt) {
            int n = wn * 32 + nt * 8 + g;
            uint2 w0 = sm.Wp[n * WSTRIDE + kp0];
            uint2 w1 = sm.Wp[n * WSTRIDE + kp0 + 4];
#pragma unroll
            for (int mt = 0; mt < 2; ++mt) {
                MMA_BF16(acc[mt][nt], Ah[mt][0], Ah[mt][1], Ah[mt][2], Ah[mt][3], w0.x, w1.x);
                MMA_BF16(acc[mt][nt], Al[mt][0], Al[mt][1], Al[mt][2], Al[mt][3], w0.x, w1.x);
                MMA_BF16(acc[mt][nt], Ah[mt][0], Ah[mt][1], Ah[mt][2], Ah[mt][3], w0.y, w1.y);
            }
        }
    }
    __syncthreads();   // X reads done (Ap free), W1 reads done (Wp free)

    // relu + bias -> H packed into Ap; meanwhile reload Wp with W2
    {
        const uint4* s2 = reinterpret_cast<const uint4*>(W2g);
        uint4* d2 = reinterpret_cast<uint4*>(sm.Wp);
        for (int i = tid; i < 128 * WSTRIDE / 2; i += NTHREADS) d2[i] = s2[i];
    }
    uint2* Hp = sm.Ap;
#pragma unroll
    for (int mt = 0; mt < 2; ++mt) {
#pragma unroll
        for (int nt = 0; nt < 4; ++nt) {
            int col = wn * 32 + nt * 8 + 2 * t;
            float bb0 = sm.b1[col], bb1 = sm.b1[col + 1];
            int r = rbase + mt * 16 + g;
            float h0 = fmaxf(acc[mt][nt][0] + bb0, 0.f);
            float h1 = fmaxf(acc[mt][nt][1] + bb1, 0.f);
            float h2 = fmaxf(acc[mt][nt][2] + bb0, 0.f);
            float h3 = fmaxf(acc[mt][nt][3] + bb1, 0.f);
            uint32_t hi, lo;
            split2(h0, h1, hi, lo);
            Hp[r * WSTRIDE + (col >> 1)] = make_uint2(hi, lo);
            split2(h2, h3, hi, lo);
            Hp[(r + 8) * WSTRIDE + (col >> 1)] = make_uint2(hi, lo);
        }
    }
    __syncthreads();

    // ================= stage 2: Y = H@W2 + b2 =================
#pragma unroll
    for (int a = 0; a < 2; ++a)
#pragma unroll
        for (int b = 0; b < 4; ++b)
#pragma unroll
            for (int c = 0; c < 4; ++c) acc[a][b][c] = 0.f;

#pragma unroll
    for (int ks = 0; ks < 8; ++ks) {
        const int kp0 = ks * 8 + t;
        uint32_t Ah[2][4], Al[2][4];
#pragma unroll
        for (int mt = 0; mt < 2; ++mt) {
            int r0 = rbase + mt * 16 + g;
            uint2 q0 = Hp[r0 * WSTRIDE + kp0];
            uint2 q1 = Hp[(r0 + 8) * WSTRIDE + kp0];
            uint2 q2 = Hp[r0 * WSTRIDE + kp0 + 4];
            uint2 q3 = Hp[(r0 + 8) * WSTRIDE + kp0 + 4];
            Ah[mt][0] = q0.x; Al[mt][0] = q0.y;
            Ah[mt][1] = q1.x; Al[mt][1] = q1.y;
            Ah[mt][2] = q2.x; Al[mt][2] = q2.y;
            Ah[mt][3] = q3.x; Al[mt][3] = q3.y;
        }
#pragma unroll
        for (int nt = 0; nt < 4; ++nt) {
            int n = wn * 32 + nt * 8 + g;
            uint2 w0 = sm.Wp[n * WSTRIDE + kp0];
            uint2 w1 = sm.Wp[n * WSTRIDE + kp0 + 4];
#pragma unroll
            for (int mt = 0; mt < 2; ++mt) {
                MMA_BF16(acc[mt][nt], Ah[mt][0], Ah[mt][1], Ah[mt][2], Ah[mt][3], w0.x, w1.x);
                MMA_BF16(acc[mt][nt], Al[mt][0], Al[mt][1], Al[mt][2], Al[mt][3], w0.x, w1.x);
                MMA_BF16(acc[mt][nt], Ah[mt][0], Ah[mt][1], Ah[mt][2], Ah[mt][3], w0.y, w1.y);
            }
        }
    }
    __syncthreads();   // all H reads done -> Ap free for Y

    // Y (with bias) staged into Ap region, stride 136 floats
    float* Y = reinterpret_cast<float*>(sm.Ap);
#pragma unroll
    for (int mt = 0; mt < 2; ++mt) {
#pragma unroll
        for (int nt = 0; nt < 4; ++nt) {
            int col = wn * 32 + nt * 8 + 2 * t;
            float bb0 = sm.b2[col], bb1 = sm.b2[col + 1];
            int r = rbase + mt * 16 + g;
            *reinterpret_cast<float2*>(&Y[r * 136 + col]) =
                make_float2(acc[mt][nt][0] + bb0, acc[mt][nt][1] + bb1);
            *reinterpret_cast<float2*>(&Y[(r + 8) * 136 + col]) =
                make_float2(acc[mt][nt][2] + bb0, acc[mt][nt][3] + bb1);
        }
    }
    __syncthreads();

    if (GAMMA) {
        // run-length segment-sum: thread = (col, eighth of rows)
        int c = tid & 127, part = tid >> 7;       // 1024 threads = 128 cols x 8 parts
        int r0 = part * 32, r1 = r0 + 32;
        float av = 0.f;
        int cur = sm.seg[r0];
        for (int r = r0; r < r1; ++r) {
            int s = sm.seg[r];
            if (s != cur) {
                if (cur >= 0) atomicAdd(&g_psum[cur * 128 + c], av);
                av = 0.f; cur = s;
            }
            av += Y[r * 136 + c];
        }
        if (cur >= 0) atomicAdd(&g_psum[cur * 128 + c], av);

        if (tid == 0) {
            int cur2 = sm.seg[0]; float run = 0.f;
            for (int r = 0; r < TROWS; ++r) {
                int s = sm.seg[r];
                if (s != cur2) {
                    if (cur2 >= 0) atomicAdd(&g_cnt[cur2], run);
                    run = 0.f; cur2 = s;
                }
                run += 1.f;
            }
            if (cur2 >= 0) atomicAdd(&g_cnt[cur2], run);
        }
    } else {
        // out = tanh(Y + pooled[seg]), coalesced float4
        for (int i = tid; i < TROWS * 32; i += NTHREADS) {
            int r  = i >> 5;
            int c4 = (i & 31) * 4;
            if (tile0 + r < nrows) {
                int s = sm.seg[r];
                float4 p = *reinterpret_cast<const float4*>(&g_pooled[s * 128 + c4]);
                float4 yv = *reinterpret_cast<const float4*>(&Y[r * 136 + c4]);
                float4 o;
                o.x = tanhf(yv.x + p.x);
                o.y = tanhf(yv.y + p.y);
                o.z = tanhf(yv.z + p.z);
                o.w = tanhf(yv.w + p.w);
                *reinterpret_cast<float4*>(out + (size_t)(tile0 + r) * 128 + c4) = o;
            }
        }
    }
}

// ---------------------------------------------------------------------------
extern "C" void kernel_launch(void* const* d_in, const int* in_sizes, int n_in,
                              void* d_out, int out_size) {
    const float* x    = (const float*)d_in[0];
    const int*   seg  = (const int*)d_in[1];
    const float* lW1  = (const float*)d_in[2];
    const float* lb1  = (const float*)d_in[3];
    const float* lW2  = (const float*)d_in[4];
    const float* lb2  = (const float*)d_in[5];
    const float* gW1  = (const float*)d_in[6];
    const float* gb1  = (const float*)d_in[7];
    const float* gW2  = (const float*)d_in[8];
    const float* gb2  = (const float*)d_in[9];

    int nrows = in_sizes[0] / 128;
    int tiles = (nrows + TROWS - 1) / TROWS;
    size_t smem = sizeof(SmemT);

    cudaFuncSetAttribute(mlp_kernel<1>, cudaFuncAttributeMaxDynamicSharedMemorySize, (int)smem);
    cudaFuncSetAttribute(mlp_kernel<0>, cudaFuncAttributeMaxDynamicSharedMemorySize, (int)smem);

    prep_kernel<<<128, 256>>>(lW1, lW2, gW1, gW2);
    mlp_kernel<1><<<tiles, NTHREADS, smem>>>(x, seg, gb1, gb2, nullptr, nrows);
    finalize_kernel<<<128, 256>>>();
    mlp_kernel<0><<<tiles, NTHREADS, smem>>>(x, seg, lb1, lb2, (float*)d_out, nrows);
}

// round 10
// speedup vs baseline: 1.1142x; 1.1142x over previous
#include <cuda_runtime.h>
#include <cuda_bf16.h>
#include <math.h>
#include <stdint.h>

#define S_SEG 256
#define TROWS 192
#define NTHREADS 768   // 24 warps: (wm 0..5) x (wn 0..3), warp tile 32x32

// ---- smem layout (bytes). 128 bf16 cols = 256 B payload, PITCH 272 B ----
#define PITCH   272
#define A_H_OFF 0                       // 192*272 = 52224
#define A_L_OFF 52224
#define W_OFF   104448                  // 2 planes (hi,lo) of active W matrix
#define WPLANE  34816                   // 128*272
#define B1_OFF  (W_OFF + 2 * WPLANE)    // 174080
#define B2_OFF  (B1_OFF + 512)
#define SEG_OFF (B2_OFF + 512)
#define SMEM_BYTES (SEG_OFF + TROWS * 4)   // 175872

// global scratch: weight planes [branch][W1H,W1L,W2H,W2L][128*68 words]
__device__ uint32_t g_Wp[2][4][128 * 68];
__device__ float g_psum[S_SEG * 128];
__device__ float g_cnt[S_SEG];
__device__ float g_pooled[S_SEG * 128];

__device__ __forceinline__ uint32_t smem_u32(const void* p) {
    uint32_t a;
    asm("{ .reg .u64 t; cvta.to.shared.u64 t, %1; cvt.u32.u64 %0, t; }" : "=r"(a) : "l"(p));
    return a;
}

__device__ __forceinline__ void split2(float a, float b, uint32_t& hi, uint32_t& lo) {
    __nv_bfloat16 ah = __float2bfloat16(a);
    __nv_bfloat16 bh = __float2bfloat16(b);
    __nv_bfloat16 al = __float2bfloat16(a - __bfloat162float(ah));
    __nv_bfloat16 bl = __float2bfloat16(b - __bfloat162float(bh));
    hi = ((uint32_t)__bfloat16_as_ushort(bh) << 16) | (uint32_t)__bfloat16_as_ushort(ah);
    lo = ((uint32_t)__bfloat16_as_ushort(bl) << 16) | (uint32_t)__bfloat16_as_ushort(al);
}

#define MMA_BF16(d, a, b0v, b1v)                                              \
    asm volatile(                                                             \
        "mma.sync.aligned.m16n8k16.row.col.f32.bf16.bf16.f32 "                \
        "{%0,%1,%2,%3}, {%4,%5,%6,%7}, {%8,%9}, {%0,%1,%2,%3};"               \
        : "+f"((d)[0]), "+f"((d)[1]), "+f"((d)[2]), "+f"((d)[3])              \
        : "r"((a)[0]), "r"((a)[1]), "r"((a)[2]), "r"((a)[3]),                 \
          "r"(b0v), "r"(b1v))

#define LDSM4(r, addr)                                                        \
    asm volatile("ldmatrix.sync.aligned.m8n8.x4.shared.b16 {%0,%1,%2,%3}, [%4];" \
        : "=r"((r)[0]), "=r"((r)[1]), "=r"((r)[2]), "=r"((r)[3]) : "r"(addr))

// ---------------------------------------------------------------------------
__global__ void prep_kernel(const float* __restrict__ lW1, const float* __restrict__ lW2,
                            const float* __restrict__ gW1, const float* __restrict__ gW2) {
    int tid = blockIdx.x * blockDim.x + threadIdx.x;   // 0..32767
    if (tid < S_SEG * 128) g_psum[tid] = 0.f;
    if (tid < S_SEG)       g_cnt[tid]  = 0.f;
    int m   = tid >> 13;          // 0..3: lW1,lW2,gW1,gW2
    int idx = tid & 8191;
    int n   = idx & 127;
    int kp  = idx >> 7;           // 0..63
    const float* src = (m == 0) ? lW1 : (m == 1) ? lW2 : (m == 2) ? gW1 : gW2;
    int br = m >> 1;
    int ly = (m & 1) * 2;         // W1 -> planes 0,1 ; W2 -> planes 2,3
    float a = src[(2 * kp) * 128 + n];
    float b = src[(2 * kp + 1) * 128 + n];
    uint32_t hi, lo;
    split2(a, b, hi, lo);
    g_Wp[br][ly][n * 68 + kp]     = hi;
    g_Wp[br][ly + 1][n * 68 + kp] = lo;
}

__global__ void finalize_kernel() {
    int i = blockIdx.x * blockDim.x + threadIdx.x;
    if (i < S_SEG * 128)
        g_pooled[i] = g_psum[i] / fmaxf(g_cnt[i >> 7], 1.f);
}

// ---------------------------------------------------------------------------
// one GEMM stage: acc += 3-term split product.
// A hi plane at a0, lo at a0 + A_L_OFF; W hi plane at w0, lo at w0 + WPLANE.
// ---------------------------------------------------------------------------
__device__ __forceinline__ void gemm_stage(uint32_t a0, uint32_t w0, float (&acc)[2][4][4]) {
#pragma unroll
    for (int ks = 0; ks < 8; ++ks) {
        uint32_t A0h[4], A1h[4], A0l[4], A1l[4];
        LDSM4(A0h, a0);
        LDSM4(A1h, a0 + 16 * PITCH);
        LDSM4(A0l, a0 + A_L_OFF);
        LDSM4(A1l, a0 + A_L_OFF + 16 * PITCH);
        uint32_t B0h[4], B1h[4], B0l[4], B1l[4];
        LDSM4(B0h, w0);
        LDSM4(B1h, w0 + 16 * PITCH);
        LDSM4(B0l, w0 + WPLANE);
        LDSM4(B1l, w0 + WPLANE + 16 * PITCH);

        // nt0: B0{0,2}  nt1: B0{1,3}  nt2: B1{0,2}  nt3: B1{1,3}
        MMA_BF16(acc[0][0], A0h, B0h[0], B0h[2]);
        MMA_BF16(acc[0][0], A0l, B0h[0], B0h[2]);
        MMA_BF16(acc[0][0], A0h, B0l[0], B0l[2]);
        MMA_BF16(acc[0][1], A0h, B0h[1], B0h[3]);
        MMA_BF16(acc[0][1], A0l, B0h[1], B0h[3]);
        MMA_BF16(acc[0][1], A0h, B0l[1], B0l[3]);
        MMA_BF16(acc[0][2], A0h, B1h[0], B1h[2]);
        MMA_BF16(acc[0][2], A0l, B1h[0], B1h[2]);
        MMA_BF16(acc[0][2], A0h, B1l[0], B1l[2]);
        MMA_BF16(acc[0][3], A0h, B1h[1], B1h[3]);
        MMA_BF16(acc[0][3], A0l, B1h[1], B1h[3]);
        MMA_BF16(acc[0][3], A0h, B1l[1], B1l[3]);

        MMA_BF16(acc[1][0], A1h, B0h[0], B0h[2]);
        MMA_BF16(acc[1][0], A1l, B0h[0], B0h[2]);
        MMA_BF16(acc[1][0], A1h, B0l[0], B0l[2]);
        MMA_BF16(acc[1][1], A1h, B0h[1], B0h[3]);
        MMA_BF16(acc[1][1], A1l, B0h[1], B0h[3]);
        MMA_BF16(acc[1][1], A1h, B0l[1], B0l[3]);
        MMA_BF16(acc[1][2], A1h, B1h[0], B1h[2]);
        MMA_BF16(acc[1][2], A1l, B1h[0], B1h[2]);
        MMA_BF16(acc[1][2], A1h, B1l[0], B1l[2]);
        MMA_BF16(acc[1][3], A1h, B1h[1], B1h[3]);
        MMA_BF16(acc[1][3], A1l, B1h[1], B1h[3]);
        MMA_BF16(acc[1][3], A1h, B1l[1], B1l[3]);

        a0 += 32;   // k += 16 (bf16)
        w0 += 32;
    }
}

// ---------------------------------------------------------------------------
template <int GAMMA>
__global__ void __launch_bounds__(NTHREADS, 1)
mlp_kernel(const float* __restrict__ x, const int* __restrict__ seg,
           const float* __restrict__ b1g, const float* __restrict__ b2g,
           float* __restrict__ out, int nrows) {
    extern __shared__ char smp[];
    float* sb1  = (float*)(smp + B1_OFF);
    float* sb2  = (float*)(smp + B2_OFF);
    int*   sseg = (int*)(smp + SEG_OFF);
    const uint32_t sbase = smem_u32(smp);

    const int tid   = threadIdx.x;
    const int tile0 = blockIdx.x * TROWS;

    // ---- W1 planes (hi,lo) -> smem ----
    {
        const uint4* s = (const uint4*)(&g_Wp[GAMMA][0][0]);
        uint4* d = (uint4*)(smp + W_OFF);
        for (int i = tid; i < 2 * WPLANE / 16; i += NTHREADS) d[i] = s[i];
    }
    // ---- X tile: load + hi/lo split into planes ----
    for (int i = tid; i < TROWS * 32; i += NTHREADS) {
        int r  = i >> 5;
        int c4 = (i & 31) * 4;
        float4 v = make_float4(0.f, 0.f, 0.f, 0.f);
        if (tile0 + r < nrows)
            v = *(const float4*)(x + (size_t)(tile0 + r) * 128 + c4);
        uint32_t h0, l0, h1, l1;
        split2(v.x, v.y, h0, l0);
        split2(v.z, v.w, h1, l1);
        *(uint2*)(smp + A_H_OFF + r * PITCH + c4 * 2) = make_uint2(h0, h1);
        *(uint2*)(smp + A_L_OFF + r * PITCH + c4 * 2) = make_uint2(l0, l1);
    }
    if (tid < 128) { sb1[tid] = b1g[tid]; sb2[tid] = b2g[tid]; }
    if (tid < TROWS)
        sseg[tid] = (tile0 + tid < nrows) ? seg[tile0 + tid] : -1;
    __syncthreads();

    const int lane = tid & 31, warp = tid >> 5;
    const int g = lane >> 2, t = lane & 3;
    const int wm = warp >> 2, wn = warp & 3;   // 6 x 4 warp grid
    const int rbase = wm * 32;

    // ldmatrix lane base addresses (x4: lanes 0-7 m0, 8-15 m1, 16-23 m2, 24-31 m3)
    const int lr = lane & 7, lh = (lane >> 3) & 1, lk = lane >> 4;
    const uint32_t aBase = sbase + A_H_OFF + (rbase + lr + lh * 8) * PITCH + lk * 16;
    const uint32_t wBase = sbase + W_OFF + (wn * 32 + lr + lh * 8) * PITCH + lk * 16;

    // ================= stage 1: H = relu(X@W1 + b1) =================
    float acc[2][4][4];
#pragma unroll
    for (int a = 0; a < 2; ++a)
#pragma unroll
        for (int b = 0; b < 4; ++b)
#pragma unroll
            for (int c = 0; c < 4; ++c) acc[a][b][c] = 0.f;

    gemm_stage(aBase, wBase, acc);
    __syncthreads();   // X-plane and W1 reads complete

    // reload W region with W2 planes; relu+bias -> H planes (overwrite X)
    {
        const uint4* s = (const uint4*)(&g_Wp[GAMMA][2][0]);
        uint4* d = (uint4*)(smp + W_OFF);
        for (int i = tid; i < 2 * WPLANE / 16; i += NTHREADS) d[i] = s[i];
    }
#pragma unroll
    for (int mt = 0; mt < 2; ++mt)
#pragma unroll
        for (int nt = 0; nt < 4; ++nt) {
            int c = wn * 32 + nt * 8 + 2 * t;
            float bb0 = sb1[c], bb1 = sb1[c + 1];
            int r0 = rbase + mt * 16 + g;
            float h0 = fmaxf(acc[mt][nt][0] + bb0, 0.f);
            float h1 = fmaxf(acc[mt][nt][1] + bb1, 0.f);
            float h2 = fmaxf(acc[mt][nt][2] + bb0, 0.f);
            float h3 = fmaxf(acc[mt][nt][3] + bb1, 0.f);
            uint32_t hi, lo;
            split2(h0, h1, hi, lo);
            *(uint32_t*)(smp + A_H_OFF + r0 * PITCH + c * 2) = hi;
            *(uint32_t*)(smp + A_L_OFF + r0 * PITCH + c * 2) = lo;
            split2(h2, h3, hi, lo);
            *(uint32_t*)(smp + A_H_OFF + (r0 + 8) * PITCH + c * 2) = hi;
            *(uint32_t*)(smp + A_L_OFF + (r0 + 8) * PITCH + c * 2) = lo;
        }
    __syncthreads();

    // ================= stage 2: Y = H@W2 + b2 =================
#pragma unroll
    for (int a = 0; a < 2; ++a)
#pragma unroll
        for (int b = 0; b < 4; ++b)
#pragma unroll
            for (int c = 0; c < 4; ++c) acc[a][b][c] = 0.f;

    gemm_stage(aBase, wBase, acc);

    // ================= epilogue (straight from accumulators) =================
    if (GAMMA) {
        int s0 = sseg[rbase];
        bool uni = (s0 == sseg[rbase + 31]);
        if (uni && s0 >= 0) {
            // whole 32-row strip in one segment: butterfly-reduce over row lanes
#pragma unroll
            for (int nt = 0; nt < 4; ++nt) {
                float e0 = acc[0][nt][0] + acc[0][nt][2] + acc[1][nt][0] + acc[1][nt][2];
                float e1 = acc[0][nt][1] + acc[0][nt][3] + acc[1][nt][1] + acc[1][nt][3];
#pragma unroll
                for (int off = 4; off <= 16; off <<= 1) {
                    e0 += __shfl_xor_sync(0xffffffffu, e0, off);
                    e1 += __shfl_xor_sync(0xffffffffu, e1, off);
                }
                if (lane < 4) {
                    int c = wn * 32 + nt * 8 + 2 * lane;
                    atomicAdd(&g_psum[s0 * 128 + c],     e0 + 32.f * sb2[c]);
                    atomicAdd(&g_psum[s0 * 128 + c + 1], e1 + 32.f * sb2[c + 1]);
                }
            }
        } else {
            // boundary strip (rare): per-row atomics
#pragma unroll
            for (int mt = 0; mt < 2; ++mt)
#pragma unroll
                for (int h = 0; h < 2; ++h) {
                    int r = rbase + mt * 16 + g + h * 8;
                    int s = sseg[r];
                    if (s >= 0) {
#pragma unroll
                        for (int nt = 0; nt < 4; ++nt) {
                            int c = wn * 32 + nt * 8 + 2 * t;
                            atomicAdd(&g_psum[s * 128 + c],     acc[mt][nt][2 * h]     + sb2[c]);
                            atomicAdd(&g_psum[s * 128 + c + 1], acc[mt][nt][2 * h + 1] + sb2[c + 1]);
                        }
                    }
                }
        }
        if (tid == 0) {
            int cur = sseg[0]; float run = 0.f;
            for (int r = 0; r < TROWS; ++r) {
                int s = sseg[r];
                if (s != cur) {
                    if (cur >= 0) atomicAdd(&g_cnt[cur], run);
                    run = 0.f; cur = s;
                }
                run += 1.f;
            }
            if (cur >= 0) atomicAdd(&g_cnt[cur], run);
        }
    } else {
        // lambda: out = tanh(acc + b2 + pooled[seg]), float2 stores from regs
#pragma unroll
        for (int mt = 0; mt < 2; ++mt)
#pragma unroll
            for (int h = 0; h < 2; ++h) {
                int rl = rbase + mt * 16 + g + h * 8;
                int rg = tile0 + rl;
                if (rg < nrows) {
                    const float* pr = &g_pooled[sseg[rl] * 128];
                    float* orow = out + (size_t)rg * 128;
#pragma unroll
                    for (int nt = 0; nt < 4; ++nt) {
                        int c = wn * 32 + nt * 8 + 2 * t;
                        float2 p = *(const float2*)(pr + c);
                        float2 o;
                        o.x = tanhf(acc[mt][nt][2 * h]     + sb2[c]     + p.x);
                        o.y = tanhf(acc[mt][nt][2 * h + 1] + sb2[c + 1] + p.y);
                        *(float2*)(orow + c) = o;
                    }
                }
            }
    }
}

// ---------------------------------------------------------------------------
extern "C" void kernel_launch(void* const* d_in, const int* in_sizes, int n_in,
                              void* d_out, int out_size) {
    const float* x    = (const float*)d_in[0];
    const int*   seg  = (const int*)d_in[1];
    const float* lW1  = (const float*)d_in[2];
    const float* lb1  = (const float*)d_in[3];
    const float* lW2  = (const float*)d_in[4];
    const float* lb2  = (const float*)d_in[5];
    const float* gW1  = (const float*)d_in[6];
    const float* gb1  = (const float*)d_in[7];
    const float* gW2  = (const float*)d_in[8];
    const float* gb2  = (const float*)d_in[9];

    int nrows = in_sizes[0] / 128;
    int tiles = (nrows + TROWS - 1) / TROWS;

    cudaFuncSetAttribute(mlp_kernel<1>, cudaFuncAttributeMaxDynamicSharedMemorySize, SMEM_BYTES);
    cudaFuncSetAttribute(mlp_kernel<0>, cudaFuncAttributeMaxDynamicSharedMemorySize, SMEM_BYTES);

    prep_kernel<<<128, 256>>>(lW1, lW2, gW1, gW2);
    mlp_kernel<1><<<tiles, NTHREADS, SMEM_BYTES>>>(x, seg, gb1, gb2, nullptr, nrows);
    finalize_kernel<<<128, 256>>>();
    mlp_kernel<0><<<tiles, NTHREADS, SMEM_BYTES>>>(x, seg, lb1, lb2, (float*)d_out, nrows);
}

// round 11
// speedup vs baseline: 1.3260x; 1.1901x over previous
#include <cuda_runtime.h>
#include <cuda_bf16.h>
#include <math.h>
#include <stdint.h>

#define S_SEG 256
#define TROWS 128
#define NTHREADS 512   // 16 warps: (wm 0..3) x (wn 0..3), warp tile 32x32

// ---- smem layout (bytes). 128 bf16 cols = 256 B payload, PITCH 272 B ----
#define PITCH   272
#define WPLANE  34816                   // 128*272
#define A_H_OFF 0                       // 34816
#define A_L_OFF 34816                   // 34816
#define W_OFF   69632                   // 4 planes: W1H,W1L,W2H,W2L = 139264
#define B1_OFF  (W_OFF + 4 * WPLANE)    // 208896
#define B2_OFF  (B1_OFF + 512)
#define SEG_OFF (B2_OFF + 512)          // double buffer: 2 x 512
#define SMEM_BYTES (SEG_OFF + 2 * 512)  // 210944

// global scratch: weight planes [branch][W1H,W1L,W2H,W2L][128*68 words]
__device__ uint32_t g_Wp[2][4][128 * 68];
__device__ float g_psum[S_SEG * 128];
__device__ float g_cnt[S_SEG];
__device__ float g_pooled[S_SEG * 128];

__device__ __forceinline__ uint32_t smem_u32(const void* p) {
    uint32_t a;
    asm("{ .reg .u64 t; cvta.to.shared.u64 t, %1; cvt.u32.u64 %0, t; }" : "=r"(a) : "l"(p));
    return a;
}

__device__ __forceinline__ void split2(float a, float b, uint32_t& hi, uint32_t& lo) {
    __nv_bfloat16 ah = __float2bfloat16(a);
    __nv_bfloat16 bh = __float2bfloat16(b);
    __nv_bfloat16 al = __float2bfloat16(a - __bfloat162float(ah));
    __nv_bfloat16 bl = __float2bfloat16(b - __bfloat162float(bh));
    hi = ((uint32_t)__bfloat16_as_ushort(bh) << 16) | (uint32_t)__bfloat16_as_ushort(ah);
    lo = ((uint32_t)__bfloat16_as_ushort(bl) << 16) | (uint32_t)__bfloat16_as_ushort(al);
}

#define MMA_BF16(d, a, b0v, b1v)                                              \
    asm volatile(                                                             \
        "mma.sync.aligned.m16n8k16.row.col.f32.bf16.bf16.f32 "                \
        "{%0,%1,%2,%3}, {%4,%5,%6,%7}, {%8,%9}, {%0,%1,%2,%3};"               \
        : "+f"((d)[0]), "+f"((d)[1]), "+f"((d)[2]), "+f"((d)[3])              \
        : "r"((a)[0]), "r"((a)[1]), "r"((a)[2]), "r"((a)[3]),                 \
          "r"(b0v), "r"(b1v))

#define LDSM4(r, addr)                                                        \
    asm volatile("ldmatrix.sync.aligned.m8n8.x4.shared.b16 {%0,%1,%2,%3}, [%4];" \
        : "=r"((r)[0]), "=r"((r)[1]), "=r"((r)[2]), "=r"((r)[3]) : "r"(addr))

// ---------------------------------------------------------------------------
__global__ void prep_kernel(const float* __restrict__ lW1, const float* __restrict__ lW2,
                            const float* __restrict__ gW1, const float* __restrict__ gW2) {
    int tid = blockIdx.x * blockDim.x + threadIdx.x;   // 0..32767
    if (tid < S_SEG * 128) g_psum[tid] = 0.f;
    if (tid < S_SEG)       g_cnt[tid]  = 0.f;
    int m   = tid >> 13;          // 0..3: lW1,lW2,gW1,gW2
    int idx = tid & 8191;
    int n   = idx & 127;
    int kp  = idx >> 7;           // 0..63
    const float* src = (m == 0) ? lW1 : (m == 1) ? lW2 : (m == 2) ? gW1 : gW2;
    int br = m >> 1;
    int ly = (m & 1) * 2;         // W1 -> planes 0,1 ; W2 -> planes 2,3
    float a = src[(2 * kp) * 128 + n];
    float b = src[(2 * kp + 1) * 128 + n];
    uint32_t hi, lo;
    split2(a, b, hi, lo);
    g_Wp[br][ly][n * 68 + kp]     = hi;
    g_Wp[br][ly + 1][n * 68 + kp] = lo;
}

__global__ void finalize_kernel() {
    int i = blockIdx.x * blockDim.x + threadIdx.x;
    if (i < S_SEG * 128)
        g_pooled[i] = g_psum[i] / fmaxf(g_cnt[i >> 7], 1.f);
}

// ---------------------------------------------------------------------------
// one GEMM stage: acc += 3-term split product.
// A hi plane at a0, lo at a0 + A_L_OFF; W hi plane at w0, lo at w0 + WPLANE.
// ---------------------------------------------------------------------------
__device__ __forceinline__ void gemm_stage(uint32_t a0, uint32_t w0, float (&acc)[2][4][4]) {
#pragma unroll
    for (int ks = 0; ks < 8; ++ks) {
        uint32_t A0h[4], A1h[4], A0l[4], A1l[4];
        LDSM4(A0h, a0);
        LDSM4(A1h, a0 + 16 * PITCH);
        LDSM4(A0l, a0 + A_L_OFF);
        LDSM4(A1l, a0 + A_L_OFF + 16 * PITCH);
        uint32_t B0h[4], B1h[4], B0l[4], B1l[4];
        LDSM4(B0h, w0);
        LDSM4(B1h, w0 + 16 * PITCH);
        LDSM4(B0l, w0 + WPLANE);
        LDSM4(B1l, w0 + WPLANE + 16 * PITCH);

        MMA_BF16(acc[0][0], A0h, B0h[0], B0h[2]);
        MMA_BF16(acc[0][0], A0l, B0h[0], B0h[2]);
        MMA_BF16(acc[0][0], A0h, B0l[0], B0l[2]);
        MMA_BF16(acc[0][1], A0h, B0h[1], B0h[3]);
        MMA_BF16(acc[0][1], A0l, B0h[1], B0h[3]);
        MMA_BF16(acc[0][1], A0h, B0l[1], B0l[3]);
        MMA_BF16(acc[0][2], A0h, B1h[0], B1h[2]);
        MMA_BF16(acc[0][2], A0l, B1h[0], B1h[2]);
        MMA_BF16(acc[0][2], A0h, B1l[0], B1l[2]);
        MMA_BF16(acc[0][3], A0h, B1h[1], B1h[3]);
        MMA_BF16(acc[0][3], A0l, B1h[1], B1h[3]);
        MMA_BF16(acc[0][3], A0h, B1l[1], B1l[3]);

        MMA_BF16(acc[1][0], A1h, B0h[0], B0h[2]);
        MMA_BF16(acc[1][0], A1l, B0h[0], B0h[2]);
        MMA_BF16(acc[1][0], A1h, B0l[0], B0l[2]);
        MMA_BF16(acc[1][1], A1h, B0h[1], B0h[3]);
        MMA_BF16(acc[1][1], A1l, B0h[1], B0h[3]);
        MMA_BF16(acc[1][1], A1h, B0l[1], B0l[3]);
        MMA_BF16(acc[1][2], A1h, B1h[0], B1h[2]);
        MMA_BF16(acc[1][2], A1l, B1h[0], B1h[2]);
        MMA_BF16(acc[1][2], A1h, B1l[0], B1l[2]);
        MMA_BF16(acc[1][3], A1h, B1h[1], B1h[3]);
        MMA_BF16(acc[1][3], A1l, B1h[1], B1h[3]);
        MMA_BF16(acc[1][3], A1h, B1l[1], B1l[3]);

        a0 += 32;   // k += 16 (bf16)
        w0 += 32;
    }
}

// ---------------------------------------------------------------------------
// persistent fused MLP: each CTA loops over tiles stride gridDim.x, with
// register-prefetch of the next tile's X overlapped with the GEMMs.
// ---------------------------------------------------------------------------
template <int GAMMA>
__global__ void __launch_bounds__(NTHREADS, 1)
mlp_kernel(const float* __restrict__ x, const int* __restrict__ seg,
           const float* __restrict__ b1g, const float* __restrict__ b2g,
           float* __restrict__ out, int nrows, int ntiles) {
    extern __shared__ char smp[];
    float* sb1  = (float*)(smp + B1_OFF);
    float* sb2  = (float*)(smp + B2_OFF);
    int*   sseg0 = (int*)(smp + SEG_OFF);
    int*   sseg1 = (int*)(smp + SEG_OFF + 512);
    const uint32_t sbase = smem_u32(smp);

    const int tid = threadIdx.x;

    // ---- all 4 weight planes resident for CTA lifetime ----
    {
        const uint4* s = (const uint4*)(&g_Wp[GAMMA][0][0]);
        uint4* d = (uint4*)(smp + W_OFF);
        for (int i = tid; i < 4 * WPLANE / 16; i += NTHREADS) d[i] = s[i];
    }
    if (tid < 128) { sb1[tid] = b1g[tid]; sb2[tid] = b2g[tid]; }

    // ---- first tile X: direct LDG -> split -> STS ----
    int tile = blockIdx.x;
    if (tile < ntiles) {
        const int t0 = tile * TROWS;
#pragma unroll
        for (int j = 0; j < 8; ++j) {
            int i  = tid + j * NTHREADS;
            int r  = i >> 5;
            int c4 = (i & 31) * 4;
            float4 v = make_float4(0.f, 0.f, 0.f, 0.f);
            if (t0 + r < nrows)
                v = *(const float4*)(x + (size_t)(t0 + r) * 128 + c4);
            uint32_t h0, l0, h1, l1;
            split2(v.x, v.y, h0, l0);
            split2(v.z, v.w, h1, l1);
            *(uint2*)(smp + A_H_OFF + r * PITCH + c4 * 2) = make_uint2(h0, h1);
            *(uint2*)(smp + A_L_OFF + r * PITCH + c4 * 2) = make_uint2(l0, l1);
        }
        if (tid < TROWS)
            sseg0[tid] = (t0 + tid < nrows) ? seg[t0 + tid] : -1;
    }

    const int lane = tid & 31, warp = tid >> 5;
    const int g = lane >> 2, t = lane & 3;
    const int wm = warp >> 2, wn = warp & 3;   // 4 x 4 warp grid
    const int rbase = wm * 32;

    // ldmatrix lane base addresses (x4: lanes 0-7 m0, 8-15 m1, 16-23 m2, 24-31 m3)
    const int lr = lane & 7, lh = (lane >> 3) & 1, lk = lane >> 4;
    const uint32_t aBase  = sbase + A_H_OFF + (rbase + lr + lh * 8) * PITCH + lk * 16;
    const uint32_t wBase  = sbase + W_OFF + (wn * 32 + lr + lh * 8) * PITCH + lk * 16;
    const uint32_t wBase2 = wBase + 2 * WPLANE;

    int pb = 0;    // seg buffer parity for the CURRENT tile

    for (; tile < ntiles; tile += gridDim.x) {
        const int tile0 = tile * TROWS;
        int* scur = pb ? sseg1 : sseg0;
        int* snxt = pb ? sseg0 : sseg1;
        __syncthreads();   // A planes + seg for this tile visible; prev epilogue done

        // ---- prefetch next tile X into registers (overlaps both GEMMs) ----
        const int nxt = tile + gridDim.x;
        const bool hasnext = (nxt < ntiles);
        float4 pf[8];
        int psg = -1;
        if (hasnext) {
            const int n0 = nxt * TROWS;
#pragma unroll
            for (int j = 0; j < 8; ++j) {
                int i  = tid + j * NTHREADS;
                int r  = i >> 5;
                int c4 = (i & 31) * 4;
                pf[j] = (n0 + r < nrows)
                        ? *(const float4*)(x + (size_t)(n0 + r) * 128 + c4)
                        : make_float4(0.f, 0.f, 0.f, 0.f);
            }
            if (tid < TROWS) psg = (n0 + tid < nrows) ? seg[n0 + tid] : -1;
        }

        // ================= stage 1: H = relu(X@W1 + b1) =================
        float acc[2][4][4];
#pragma unroll
        for (int a = 0; a < 2; ++a)
#pragma unroll
            for (int b = 0; b < 4; ++b)
#pragma unroll
                for (int c = 0; c < 4; ++c) acc[a][b][c] = 0.f;

        gemm_stage(aBase, wBase, acc);
        __syncthreads();   // X reads complete -> A planes free for H

#pragma unroll
        for (int mt = 0; mt < 2; ++mt)
#pragma unroll
            for (int nt = 0; nt < 4; ++nt) {
                int c = wn * 32 + nt * 8 + 2 * t;
                float bb0 = sb1[c], bb1 = sb1[c + 1];
                int r0 = rbase + mt * 16 + g;
                float h0 = fmaxf(acc[mt][nt][0] + bb0, 0.f);
                float h1 = fmaxf(acc[mt][nt][1] + bb1, 0.f);
                float h2 = fmaxf(acc[mt][nt][2] + bb0, 0.f);
                float h3 = fmaxf(acc[mt][nt][3] + bb1, 0.f);
                uint32_t hi, lo;
                split2(h0, h1, hi, lo);
                *(uint32_t*)(smp + A_H_OFF + r0 * PITCH + c * 2) = hi;
                *(uint32_t*)(smp + A_L_OFF + r0 * PITCH + c * 2) = lo;
                split2(h2, h3, hi, lo);
                *(uint32_t*)(smp + A_H_OFF + (r0 + 8) * PITCH + c * 2) = hi;
                *(uint32_t*)(smp + A_L_OFF + (r0 + 8) * PITCH + c * 2) = lo;
            }
        __syncthreads();   // H ready

        // ================= stage 2: Y = H@W2 + b2 =================
#pragma unroll
        for (int a = 0; a < 2; ++a)
#pragma unroll
            for (int b = 0; b < 4; ++b)
#pragma unroll
                for (int c = 0; c < 4; ++c) acc[a][b][c] = 0.f;

        gemm_stage(aBase, wBase2, acc);
        __syncthreads();   // H reads complete -> A planes free for next X

        // ---- store prefetched next-tile X into A planes ----
        if (hasnext) {
#pragma unroll
            for (int j = 0; j < 8; ++j) {
                int i  = tid + j * NTHREADS;
                int r  = i >> 5;
                int c4 = (i & 31) * 4;
                uint32_t h0, l0, h1, l1;
                split2(pf[j].x, pf[j].y, h0, l0);
                split2(pf[j].z, pf[j].w, h1, l1);
                *(uint2*)(smp + A_H_OFF + r * PITCH + c4 * 2) = make_uint2(h0, h1);
                *(uint2*)(smp + A_L_OFF + r * PITCH + c4 * 2) = make_uint2(l0, l1);
            }
            if (tid < TROWS) snxt[tid] = psg;
        }

        // ================= epilogue (straight from accumulators) =================
        if (GAMMA) {
            int s0 = scur[rbase];
            bool uni = (s0 == scur[rbase + 31]);
            if (uni && s0 >= 0) {
#pragma unroll
                for (int nt = 0; nt < 4; ++nt) {
                    float e0 = acc[0][nt][0] + acc[0][nt][2] + acc[1][nt][0] + acc[1][nt][2];
                    float e1 = acc[0][nt][1] + acc[0][nt][3] + acc[1][nt][1] + acc[1][nt][3];
#pragma unroll
                    for (int off = 4; off <= 16; off <<= 1) {
                        e0 += __shfl_xor_sync(0xffffffffu, e0, off);
                        e1 += __shfl_xor_sync(0xffffffffu, e1, off);
                    }
                    if (lane < 4) {
                        int c = wn * 32 + nt * 8 + 2 * lane;
                        atomicAdd(&g_psum[s0 * 128 + c],     e0 + 32.f * sb2[c]);
                        atomicAdd(&g_psum[s0 * 128 + c + 1], e1 + 32.f * sb2[c + 1]);
                    }
                }
            } else {
#pragma unroll
                for (int mt = 0; mt < 2; ++mt)
#pragma unroll
                    for (int h = 0; h < 2; ++h) {
                        int r = rbase + mt * 16 + g + h * 8;
                        int s = scur[r];
                        if (s >= 0) {
#pragma unroll
                            for (int nt = 0; nt < 4; ++nt) {
                                int c = wn * 32 + nt * 8 + 2 * t;
                                atomicAdd(&g_psum[s * 128 + c],     acc[mt][nt][2 * h]     + sb2[c]);
                                atomicAdd(&g_psum[s * 128 + c + 1], acc[mt][nt][2 * h + 1] + sb2[c + 1]);
                            }
                        }
                    }
            }
            if (tid == 0) {
                int cur = scur[0]; float run = 0.f;
                for (int r = 0; r < TROWS; ++r) {
                    int s = scur[r];
                    if (s != cur) {
                        if (cur >= 0) atomicAdd(&g_cnt[cur], run);
                        run = 0.f; cur = s;
                    }
                    run += 1.f;
                }
                if (cur >= 0) atomicAdd(&g_cnt[cur], run);
            }
        } else {
#pragma unroll
            for (int mt = 0; mt < 2; ++mt)
#pragma unroll
                for (int h = 0; h < 2; ++h) {
                    int rl = rbase + mt * 16 + g + h * 8;
                    int rg = tile0 + rl;
                    if (rg < nrows) {
                        const float* pr = &g_pooled[scur[rl] * 128];
                        float* orow = out + (size_t)rg * 128;
#pragma unroll
                        for (int nt = 0; nt < 4; ++nt) {
                            int c = wn * 32 + nt * 8 + 2 * t;
                            float2 p = *(const float2*)(pr + c);
                            float2 o;
                            o.x = tanhf(acc[mt][nt][2 * h]     + sb2[c]     + p.x);
                            o.y = tanhf(acc[mt][nt][2 * h + 1] + sb2[c + 1] + p.y);
                            *(float2*)(orow + c) = o;
                        }
                    }
                }
        }
        pb ^= 1;
    }
}

// ---------------------------------------------------------------------------
extern "C" void kernel_launch(void* const* d_in, const int* in_sizes, int n_in,
                              void* d_out, int out_size) {
    const float* x    = (const float*)d_in[0];
    const int*   seg  = (const int*)d_in[1];
    const float* lW1  = (const float*)d_in[2];
    const float* lb1  = (const float*)d_in[3];
    const float* lW2  = (const float*)d_in[4];
    const float* lb2  = (const float*)d_in[5];
    const float* gW1  = (const float*)d_in[6];
    const float* gb1  = (const float*)d_in[7];
    const float* gW2  = (const float*)d_in[8];
    const float* gb2  = (const float*)d_in[9];

    int nrows  = in_sizes[0] / 128;
    int ntiles = (nrows + TROWS - 1) / TROWS;

    int nsm = 148;
    cudaDeviceGetAttribute(&nsm, cudaDevAttrMultiProcessorCount, 0);
    if (nsm <= 0) nsm = 148;
    if (nsm > ntiles) nsm = ntiles;

    cudaFuncSetAttribute(mlp_kernel<1>, cudaFuncAttributeMaxDynamicSharedMemorySize, SMEM_BYTES);
    cudaFuncSetAttribute(mlp_kernel<0>, cudaFuncAttributeMaxDynamicSharedMemorySize, SMEM_BYTES);

    prep_kernel<<<128, 256>>>(lW1, lW2, gW1, gW2);
    mlp_kernel<1><<<nsm, NTHREADS, SMEM_BYTES>>>(x, seg, gb1, gb2, nullptr, nrows, ntiles);
    finalize_kernel<<<128, 256>>>();
    mlp_kernel<0><<<nsm, NTHREADS, SMEM_BYTES>>>(x, seg, lb1, lb2, (float*)d_out, nrows, ntiles);
}

// round 12
// speedup vs baseline: 1.4455x; 1.0901x over previous
#include <cuda_runtime.h>
#include <cuda_bf16.h>
#include <math.h>
#include <stdint.h>

#define S_SEG 256
#define TROWS 64       // rows per GROUP tile
#define NTHREADS 512   // 2 groups x 8 warps; group warp grid (wm 0..1) x (wn 0..3)

// ---- smem layout (bytes). 128 bf16 cols = 256 B payload, PITCH 272 B ----
#define PITCH   272
#define HPLANE  17408                   // 64*272 (group A half-plane)
#define WPLANE  34816                   // 128*272
#define A_OFF   0                       // [G0H, G0L, G1H, G1L] = 69632
#define W_OFF   69632                   // W1H,W1L,W2H,W2L = 139264
#define B1_OFF  (W_OFF + 4 * WPLANE)    // 208896
#define B2_OFF  (B1_OFF + 512)          // 209408
#define SEG_OFF (B2_OFF + 512)          // 2 groups x 2 parity x 256 B
#define SMEM_BYTES (SEG_OFF + 1024)     // 210944

// global scratch: weight planes [branch][W1H,W1L,W2H,W2L][128*68 words]
__device__ uint32_t g_Wp[2][4][128 * 68];
__device__ float g_psum[S_SEG * 128];
__device__ float g_cnt[S_SEG];
__device__ float g_pooled[S_SEG * 128];

__device__ __forceinline__ uint32_t smem_u32(const void* p) {
    uint32_t a;
    asm("{ .reg .u64 t; cvta.to.shared.u64 t, %1; cvt.u32.u64 %0, t; }" : "=r"(a) : "l"(p));
    return a;
}

__device__ __forceinline__ void split2(float a, float b, uint32_t& hi, uint32_t& lo) {
    __nv_bfloat16 ah = __float2bfloat16(a);
    __nv_bfloat16 bh = __float2bfloat16(b);
    __nv_bfloat16 al = __float2bfloat16(a - __bfloat162float(ah));
    __nv_bfloat16 bl = __float2bfloat16(b - __bfloat162float(bh));
    hi = ((uint32_t)__bfloat16_as_ushort(bh) << 16) | (uint32_t)__bfloat16_as_ushort(ah);
    lo = ((uint32_t)__bfloat16_as_ushort(bl) << 16) | (uint32_t)__bfloat16_as_ushort(al);
}

#define MMA_BF16(d, a, b0v, b1v)                                              \
    asm volatile(                                                             \
        "mma.sync.aligned.m16n8k16.row.col.f32.bf16.bf16.f32 "                \
        "{%0,%1,%2,%3}, {%4,%5,%6,%7}, {%8,%9}, {%0,%1,%2,%3};"               \
        : "+f"((d)[0]), "+f"((d)[1]), "+f"((d)[2]), "+f"((d)[3])              \
        : "r"((a)[0]), "r"((a)[1]), "r"((a)[2]), "r"((a)[3]),                 \
          "r"(b0v), "r"(b1v))

#define LDSM4(r, addr)                                                        \
    asm volatile("ldmatrix.sync.aligned.m8n8.x4.shared.b16 {%0,%1,%2,%3}, [%4];" \
        : "=r"((r)[0]), "=r"((r)[1]), "=r"((r)[2]), "=r"((r)[3]) : "r"(addr))

#define BARG(id)                                                              \
    asm volatile("bar.sync %0, 256;" :: "r"(id) : "memory")

// ---------------------------------------------------------------------------
__global__ void prep_kernel(const float* __restrict__ lW1, const float* __restrict__ lW2,
                            const float* __restrict__ gW1, const float* __restrict__ gW2) {
    int tid = blockIdx.x * blockDim.x + threadIdx.x;   // 0..32767
    if (tid < S_SEG * 128) g_psum[tid] = 0.f;
    if (tid < S_SEG)       g_cnt[tid]  = 0.f;
    int m   = tid >> 13;          // 0..3: lW1,lW2,gW1,gW2
    int idx = tid & 8191;
    int n   = idx & 127;
    int kp  = idx >> 7;           // 0..63
    const float* src = (m == 0) ? lW1 : (m == 1) ? lW2 : (m == 2) ? gW1 : gW2;
    int br = m >> 1;
    int ly = (m & 1) * 2;         // W1 -> planes 0,1 ; W2 -> planes 2,3
    float a = src[(2 * kp) * 128 + n];
    float b = src[(2 * kp + 1) * 128 + n];
    uint32_t hi, lo;
    split2(a, b, hi, lo);
    g_Wp[br][ly][n * 68 + kp]     = hi;
    g_Wp[br][ly + 1][n * 68 + kp] = lo;
}

__global__ void finalize_kernel() {
    int i = blockIdx.x * blockDim.x + threadIdx.x;
    if (i < S_SEG * 128)
        g_pooled[i] = g_psum[i] / fmaxf(g_cnt[i >> 7], 1.f);
}

// ---------------------------------------------------------------------------
// one GEMM stage: acc += 3-term split product.
// A hi plane at a0, lo at a0 + HPLANE; W hi plane at w0, lo at w0 + WPLANE.
// ---------------------------------------------------------------------------
__device__ __forceinline__ void gemm_stage(uint32_t a0, uint32_t w0, float (&acc)[2][4][4]) {
#pragma unroll
    for (int ks = 0; ks < 8; ++ks) {
        uint32_t A0h[4], A1h[4], A0l[4], A1l[4];
        LDSM4(A0h, a0);
        LDSM4(A1h, a0 + 16 * PITCH);
        LDSM4(A0l, a0 + HPLANE);
        LDSM4(A1l, a0 + HPLANE + 16 * PITCH);
        uint32_t B0h[4], B1h[4], B0l[4], B1l[4];
        LDSM4(B0h, w0);
        LDSM4(B1h, w0 + 16 * PITCH);
        LDSM4(B0l, w0 + WPLANE);
        LDSM4(B1l, w0 + WPLANE + 16 * PITCH);

        MMA_BF16(acc[0][0], A0h, B0h[0], B0h[2]);
        MMA_BF16(acc[0][0], A0l, B0h[0], B0h[2]);
        MMA_BF16(acc[0][0], A0h, B0l[0], B0l[2]);
        MMA_BF16(acc[0][1], A0h, B0h[1], B0h[3]);
        MMA_BF16(acc[0][1], A0l, B0h[1], B0h[3]);
        MMA_BF16(acc[0][1], A0h, B0l[1], B0l[3]);
        MMA_BF16(acc[0][2], A0h, B1h[0], B1h[2]);
        MMA_BF16(acc[0][2], A0l, B1h[0], B1h[2]);
        MMA_BF16(acc[0][2], A0h, B1l[0], B1l[2]);
        MMA_BF16(acc[0][3], A0h, B1h[1], B1h[3]);
        MMA_BF16(acc[0][3], A0l, B1h[1], B1h[3]);
        MMA_BF16(acc[0][3], A0h, B1l[1], B1l[3]);

        MMA_BF16(acc[1][0], A1h, B0h[0], B0h[2]);
        MMA_BF16(acc[1][0], A1l, B0h[0], B0h[2]);
        MMA_BF16(acc[1][0], A1h, B0l[0], B0l[2]);
        MMA_BF16(acc[1][1], A1h, B0h[1], B0h[3]);
        MMA_BF16(acc[1][1], A1l, B0h[1], B0h[3]);
        MMA_BF16(acc[1][1], A1h, B0l[1], B0l[3]);
        MMA_BF16(acc[1][2], A1h, B1h[0], B1h[2]);
        MMA_BF16(acc[1][2], A1l, B1h[0], B1h[2]);
        MMA_BF16(acc[1][2], A1h, B1l[0], B1l[2]);
        MMA_BF16(acc[1][3], A1h, B1h[1], B1h[3]);
        MMA_BF16(acc[1][3], A1l, B1h[1], B1h[3]);
        MMA_BF16(acc[1][3], A1h, B1l[1], B1l[3]);

        a0 += 32;   // k += 16 (bf16)
        w0 += 32;
    }
}

// ---------------------------------------------------------------------------
// persistent fused MLP, two independent 8-warp pipelines per CTA.
// Group grp (0/1): warps grp*8 .. grp*8+7, own A planes + named barrier.
// ---------------------------------------------------------------------------
template <int GAMMA>
__global__ void __launch_bounds__(NTHREADS, 1)
mlp_kernel(const float* __restrict__ x, const int* __restrict__ seg,
           const float* __restrict__ b1g, const float* __restrict__ b2g,
           float* __restrict__ out, int nrows, int ntiles) {
    extern __shared__ char smp[];
    float* sb1 = (float*)(smp + B1_OFF);
    float* sb2 = (float*)(smp + B2_OFF);
    const uint32_t sbase = smem_u32(smp);

    const int tid  = threadIdx.x;
    const int grp  = tid >> 8;          // 0 or 1
    const int gtid = tid & 255;
    const int bid  = grp + 1;           // named barrier id

    char* Aplane = smp + A_OFF + grp * 2 * HPLANE;    // hi; lo at +HPLANE
    int*  sseg0  = (int*)(smp + SEG_OFF + grp * 512);
    int*  sseg1  = (int*)(smp + SEG_OFF + grp * 512 + 256);

    // ---- all 4 weight planes resident for CTA lifetime ----
    {
        const uint4* s = (const uint4*)(&g_Wp[GAMMA][0][0]);
        uint4* d = (uint4*)(smp + W_OFF);
        for (int i = tid; i < 4 * WPLANE / 16; i += NTHREADS) d[i] = s[i];
    }
    if (tid < 128) { sb1[tid] = b1g[tid]; sb2[tid] = b2g[tid]; }

    // ---- first group tile: direct LDG -> split -> STS ----
    int tile = blockIdx.x * 2 + grp;
    if (tile < ntiles) {
        const int t0 = tile * TROWS;
#pragma unroll
        for (int j = 0; j < 8; ++j) {
            int i  = gtid + j * 256;
            int r  = i >> 5;
            int c4 = (i & 31) * 4;
            float4 v = make_float4(0.f, 0.f, 0.f, 0.f);
            if (t0 + r < nrows)
                v = *(const float4*)(x + (size_t)(t0 + r) * 128 + c4);
            uint32_t h0, l0, h1, l1;
            split2(v.x, v.y, h0, l0);
            split2(v.z, v.w, h1, l1);
            *(uint2*)(Aplane + r * PITCH + c4 * 2)          = make_uint2(h0, h1);
            *(uint2*)(Aplane + HPLANE + r * PITCH + c4 * 2) = make_uint2(l0, l1);
        }
        if (gtid < TROWS)
            sseg0[gtid] = (t0 + gtid < nrows) ? seg[t0 + gtid] : -1;
    }
    __syncthreads();    // weights + biases visible to both groups

    const int lane = tid & 31, gwarp = (tid >> 5) & 7;
    const int gq = lane >> 2, t = lane & 3;
    const int wm = gwarp >> 2, wn = gwarp & 3;   // 2 x 4 warp grid per group
    const int rbase = wm * 32;

    // ldmatrix lane base addresses
    const int lr = lane & 7, lh = (lane >> 3) & 1, lk = lane >> 4;
    const uint32_t aBase  = sbase + A_OFF + grp * 2 * HPLANE
                          + (rbase + lr + lh * 8) * PITCH + lk * 16;
    const uint32_t wBase  = sbase + W_OFF + (wn * 32 + lr + lh * 8) * PITCH + lk * 16;
    const uint32_t wBase2 = wBase + 2 * WPLANE;

    int pb = 0;
    const int stride = gridDim.x * 2;

    for (; tile < ntiles; tile += stride) {
        const int tile0 = tile * TROWS;
        int* scur = pb ? sseg1 : sseg0;
        int* snxt = pb ? sseg0 : sseg1;
        BARG(bid);     // A planes + seg visible; prev epilogue reads done

        // ---- prefetch next group tile into registers ----
        const int nxt = tile + stride;
        const bool hasnext = (nxt < ntiles);
        float4 pf[8];
        int psg = -1;
        if (hasnext) {
            const int n0 = nxt * TROWS;
#pragma unroll
            for (int j = 0; j < 8; ++j) {
                int i  = gtid + j * 256;
                int r  = i >> 5;
                int c4 = (i & 31) * 4;
                pf[j] = (n0 + r < nrows)
                        ? *(const float4*)(x + (size_t)(n0 + r) * 128 + c4)
                        : make_float4(0.f, 0.f, 0.f, 0.f);
            }
            if (gtid < TROWS) psg = (n0 + gtid < nrows) ? seg[n0 + gtid] : -1;
        }

        // ================= stage 1: H = relu(X@W1 + b1) =================
        float acc[2][4][4];
#pragma unroll
        for (int a = 0; a < 2; ++a)
#pragma unroll
            for (int b = 0; b < 4; ++b)
#pragma unroll
                for (int c = 0; c < 4; ++c) acc[a][b][c] = 0.f;

        gemm_stage(aBase, wBase, acc);
        BARG(bid);     // X reads complete -> A planes free for H

#pragma unroll
        for (int mt = 0; mt < 2; ++mt)
#pragma unroll
            for (int nt = 0; nt < 4; ++nt) {
                int c = wn * 32 + nt * 8 + 2 * t;
                float bb0 = sb1[c], bb1 = sb1[c + 1];
                int r0 = rbase + mt * 16 + gq;
                float h0 = fmaxf(acc[mt][nt][0] + bb0, 0.f);
                float h1 = fmaxf(acc[mt][nt][1] + bb1, 0.f);
                float h2 = fmaxf(acc[mt][nt][2] + bb0, 0.f);
                float h3 = fmaxf(acc[mt][nt][3] + bb1, 0.f);
                uint32_t hi, lo;
                split2(h0, h1, hi, lo);
                *(uint32_t*)(Aplane + r0 * PITCH + c * 2)          = hi;
                *(uint32_t*)(Aplane + HPLANE + r0 * PITCH + c * 2) = lo;
                split2(h2, h3, hi, lo);
                *(uint32_t*)(Aplane + (r0 + 8) * PITCH + c * 2)          = hi;
                *(uint32_t*)(Aplane + HPLANE + (r0 + 8) * PITCH + c * 2) = lo;
            }
        BARG(bid);     // H ready

        // ================= stage 2: Y = H@W2 + b2 =================
#pragma unroll
        for (int a = 0; a < 2; ++a)
#pragma unroll
            for (int b = 0; b < 4; ++b)
#pragma unroll
                for (int c = 0; c < 4; ++c) acc[a][b][c] = 0.f;

        gemm_stage(aBase, wBase2, acc);
        BARG(bid);     // H reads complete -> A planes free for next X

        // ---- store prefetched next-tile X into A planes ----
        if (hasnext) {
#pragma unroll
            for (int j = 0; j < 8; ++j) {
                int i  = gtid + j * 256;
                int r  = i >> 5;
                int c4 = (i & 31) * 4;
                uint32_t h0, l0, h1, l1;
                split2(pf[j].x, pf[j].y, h0, l0);
                split2(pf[j].z, pf[j].w, h1, l1);
                *(uint2*)(Aplane + r * PITCH + c4 * 2)          = make_uint2(h0, h1);
                *(uint2*)(Aplane + HPLANE + r * PITCH + c4 * 2) = make_uint2(l0, l1);
            }
            if (gtid < TROWS) snxt[gtid] = psg;
        }

        // ================= epilogue (straight from accumulators) =================
        if (GAMMA) {
            int s0 = scur[rbase];
            bool uni = (s0 == scur[rbase + 31]);
            if (uni && s0 >= 0) {
#pragma unroll
                for (int nt = 0; nt < 4; ++nt) {
                    float e0 = acc[0][nt][0] + acc[0][nt][2] + acc[1][nt][0] + acc[1][nt][2];
                    float e1 = acc[0][nt][1] + acc[0][nt][3] + acc[1][nt][1] + acc[1][nt][3];
#pragma unroll
                    for (int off = 4; off <= 16; off <<= 1) {
                        e0 += __shfl_xor_sync(0xffffffffu, e0, off);
                        e1 += __shfl_xor_sync(0xffffffffu, e1, off);
                    }
                    if (lane < 4) {
                        int c = wn * 32 + nt * 8 + 2 * lane;
                        atomicAdd(&g_psum[s0 * 128 + c],     e0 + 32.f * sb2[c]);
                        atomicAdd(&g_psum[s0 * 128 + c + 1], e1 + 32.f * sb2[c + 1]);
                    }
                }
            } else {
#pragma unroll
                for (int mt = 0; mt < 2; ++mt)
#pragma unroll
                    for (int h = 0; h < 2; ++h) {
                        int r = rbase + mt * 16 + gq + h * 8;
                        int s = scur[r];
                        if (s >= 0) {
#pragma unroll
                            for (int nt = 0; nt < 4; ++nt) {
                                int c = wn * 32 + nt * 8 + 2 * t;
                                atomicAdd(&g_psum[s * 128 + c],     acc[mt][nt][2 * h]     + sb2[c]);
                                atomicAdd(&g_psum[s * 128 + c + 1], acc[mt][nt][2 * h + 1] + sb2[c + 1]);
                            }
                        }
                    }
            }
            if (gtid == 0) {
                int cur = scur[0]; float run = 0.f;
                for (int r = 0; r < TROWS; ++r) {
                    int s = scur[r];
                    if (s != cur) {
                        if (cur >= 0) atomicAdd(&g_cnt[cur], run);
                        run = 0.f; cur = s;
                    }
                    run += 1.f;
                }
                if (cur >= 0) atomicAdd(&g_cnt[cur], run);
            }
        } else {
#pragma unroll
            for (int mt = 0; mt < 2; ++mt)
#pragma unroll
                for (int h = 0; h < 2; ++h) {
                    int rl = rbase + mt * 16 + gq + h * 8;
                    int rg = tile0 + rl;
                    if (rg < nrows) {
                        const float* pr = &g_pooled[scur[rl] * 128];
                        float* orow = out + (size_t)rg * 128;
#pragma unroll
                        for (int nt = 0; nt < 4; ++nt) {
                            int c = wn * 32 + nt * 8 + 2 * t;
                            float2 p = *(const float2*)(pr + c);
                            float2 o;
                            o.x = tanhf(acc[mt][nt][2 * h]     + sb2[c]     + p.x);
                            o.y = tanhf(acc[mt][nt][2 * h + 1] + sb2[c + 1] + p.y);
                            *(float2*)(orow + c) = o;
                        }
                    }
                }
        }
        pb ^= 1;
    }
}

// ---------------------------------------------------------------------------
extern "C" void kernel_launch(void* const* d_in, const int* in_sizes, int n_in,
                              void* d_out, int out_size) {
    const float* x    = (const float*)d_in[0];
    const int*   seg  = (const int*)d_in[1];
    const float* lW1  = (const float*)d_in[2];
    const float* lb1  = (const float*)d_in[3];
    const float* lW2  = (const float*)d_in[4];
    const float* lb2  = (const float*)d_in[5];
    const float* gW1  = (const float*)d_in[6];
    const float* gb1  = (const float*)d_in[7];
    const float* gW2  = (const float*)d_in[8];
    const float* gb2  = (const float*)d_in[9];

    int nrows  = in_sizes[0] / 128;
    int ntiles = (nrows + TROWS - 1) / TROWS;

    int nsm = 148;
    cudaDeviceGetAttribute(&nsm, cudaDevAttrMultiProcessorCount, 0);
    if (nsm <= 0) nsm = 148;
    int maxcta = (ntiles + 1) / 2;
    if (nsm > maxcta) nsm = maxcta;

    cudaFuncSetAttribute(mlp_kernel<1>, cudaFuncAttributeMaxDynamicSharedMemorySize, SMEM_BYTES);
    cudaFuncSetAttribute(mlp_kernel<0>, cudaFuncAttributeMaxDynamicSharedMemorySize, SMEM_BYTES);

    prep_kernel<<<128, 256>>>(lW1, lW2, gW1, gW2);
    mlp_kernel<1><<<nsm, NTHREADS, SMEM_BYTES>>>(x, seg, gb1, gb2, nullptr, nrows, ntiles);
    finalize_kernel<<<128, 256>>>();
    mlp_kernel<0><<<nsm, NTHREADS, SMEM_BYTES>>>(x, seg, lb1, lb2, (float*)d_out, nrows, ntiles);
}

// round 13
// speedup vs baseline: 1.6771x; 1.1602x over previous
#include <cuda_runtime.h>
#include <cuda_bf16.h>
#include <math.h>
#include <stdint.h>

#define S_SEG 256
#define NTHREADS 512   // 16 warps = 4 quadrants x 4 warps; quadrant owns 32 rows

// ---- smem layout (bytes). 128 bf16 cols = 256 B payload, PITCH 272 B ----
#define PITCH   272
#define WPLANE  34816                   // 128*272
#define A_L_OFF 34816                   // A: hi plane [0,34816), lo plane [34816,69632)
#define W_OFF   69632                   // W1H,W1L,W2H,W2L = 139264
#define B1_OFF  (W_OFF + 4 * WPLANE)    // 208896
#define B2_OFF  (B1_OFF + 512)          // 209408
#define SEG_OFF (B2_OFF + 512)          // 4 quadrants x 2 parity x 128 B
#define SMEM_BYTES (SEG_OFF + 1024)     // 210944

// global scratch: weight planes [branch][W1H,W1L,W2H,W2L][128*68 words]
__device__ uint32_t g_Wp[2][4][128 * 68];
__device__ float g_psum[S_SEG * 128];
__device__ float g_cnt[S_SEG];
__device__ float g_pooled[S_SEG * 128];

__device__ __forceinline__ uint32_t smem_u32(const void* p) {
    uint32_t a;
    asm("{ .reg .u64 t; cvta.to.shared.u64 t, %1; cvt.u32.u64 %0, t; }" : "=r"(a) : "l"(p));
    return a;
}

// hi = {bf16(b),bf16(a)}, lo = {bf16(b-hi.b),bf16(a-hi.a)} - 6 instructions
__device__ __forceinline__ void split2(float a, float b, uint32_t& hi, uint32_t& lo) {
    asm("cvt.rn.satfinite.bf16x2.f32 %0, %1, %2;" : "=r"(hi) : "f"(b), "f"(a));
    float af = __uint_as_float(hi << 16);
    float bf = __uint_as_float(hi & 0xffff0000u);
    float ar = a - af;
    float br = b - bf;
    asm("cvt.rn.satfinite.bf16x2.f32 %0, %1, %2;" : "=r"(lo) : "f"(br), "f"(ar));
}

#define MMA_BF16(d, a, b0v, b1v)                                              \
    asm volatile(                                                             \
        "mma.sync.aligned.m16n8k16.row.col.f32.bf16.bf16.f32 "                \
        "{%0,%1,%2,%3}, {%4,%5,%6,%7}, {%8,%9}, {%0,%1,%2,%3};"               \
        : "+f"((d)[0]), "+f"((d)[1]), "+f"((d)[2]), "+f"((d)[3])              \
        : "r"((a)[0]), "r"((a)[1]), "r"((a)[2]), "r"((a)[3]),                 \
          "r"(b0v), "r"(b1v))

#define LDSM4(r, addr)                                                        \
    asm volatile("ldmatrix.sync.aligned.m8n8.x4.shared.b16 {%0,%1,%2,%3}, [%4];" \
        : "=r"((r)[0]), "=r"((r)[1]), "=r"((r)[2]), "=r"((r)[3]) : "r"(addr))

// per-quadrant barrier: 4 consecutive warps = 128 threads, named barrier wm+1
#define BARQ(id)                                                              \
    asm volatile("bar.sync %0, 128;" :: "r"(id) : "memory")

// ---------------------------------------------------------------------------
__global__ void prep_kernel(const float* __restrict__ lW1, const float* __restrict__ lW2,
                            const float* __restrict__ gW1, const float* __restrict__ gW2) {
    int tid = blockIdx.x * blockDim.x + threadIdx.x;   // 0..32767
    if (tid < S_SEG * 128) g_psum[tid] = 0.f;
    if (tid < S_SEG)       g_cnt[tid]  = 0.f;
    int m   = tid >> 13;          // 0..3: lW1,lW2,gW1,gW2
    int idx = tid & 8191;
    int n   = idx & 127;
    int kp  = idx >> 7;           // 0..63
    const float* src = (m == 0) ? lW1 : (m == 1) ? lW2 : (m == 2) ? gW1 : gW2;
    int br = m >> 1;
    int ly = (m & 1) * 2;         // W1 -> planes 0,1 ; W2 -> planes 2,3
    float a = src[(2 * kp) * 128 + n];
    float b = src[(2 * kp + 1) * 128 + n];
    uint32_t hi, lo;
    split2(a, b, hi, lo);
    g_Wp[br][ly][n * 68 + kp]     = hi;
    g_Wp[br][ly + 1][n * 68 + kp] = lo;
}

__global__ void finalize_kernel() {
    int i = blockIdx.x * blockDim.x + threadIdx.x;
    if (i < S_SEG * 128)
        g_pooled[i] = g_psum[i] / fmaxf(g_cnt[i >> 7], 1.f);
}

// ---------------------------------------------------------------------------
// one GEMM stage: acc += 3-term split product (8 k-steps of 16).
// A hi plane at a0, lo at a0 + A_L_OFF; W hi plane at w0, lo at w0 + WPLANE.
// ---------------------------------------------------------------------------
__device__ __forceinline__ void gemm_stage(uint32_t a0, uint32_t w0, float (&acc)[2][4][4]) {
#pragma unroll
    for (int ks = 0; ks < 8; ++ks) {
        uint32_t A0h[4], A1h[4], A0l[4], A1l[4];
        LDSM4(A0h, a0);
        LDSM4(A1h, a0 + 16 * PITCH);
        LDSM4(A0l, a0 + A_L_OFF);
        LDSM4(A1l, a0 + A_L_OFF + 16 * PITCH);
        uint32_t B0h[4], B1h[4], B0l[4], B1l[4];
        LDSM4(B0h, w0);
        LDSM4(B1h, w0 + 16 * PITCH);
        LDSM4(B0l, w0 + WPLANE);
        LDSM4(B1l, w0 + WPLANE + 16 * PITCH);

        MMA_BF16(acc[0][0], A0h, B0h[0], B0h[2]);
        MMA_BF16(acc[0][0], A0l, B0h[0], B0h[2]);
        MMA_BF16(acc[0][0], A0h, B0l[0], B0l[2]);
        MMA_BF16(acc[0][1], A0h, B0h[1], B0h[3]);
        MMA_BF16(acc[0][1], A0l, B0h[1], B0h[3]);
        MMA_BF16(acc[0][1], A0h, B0l[1], B0l[3]);
        MMA_BF16(acc[0][2], A0h, B1h[0], B1h[2]);
        MMA_BF16(acc[0][2], A0l, B1h[0], B1h[2]);
        MMA_BF16(acc[0][2], A0h, B1l[0], B1l[2]);
        MMA_BF16(acc[0][3], A0h, B1h[1], B1h[3]);
        MMA_BF16(acc[0][3], A0l, B1h[1], B1h[3]);
        MMA_BF16(acc[0][3], A0h, B1l[1], B1l[3]);

        MMA_BF16(acc[1][0], A1h, B0h[0], B0h[2]);
        MMA_BF16(acc[1][0], A1l, B0h[0], B0h[2]);
        MMA_BF16(acc[1][0], A1h, B0l[0], B0l[2]);
        MMA_BF16(acc[1][1], A1h, B0h[1], B0h[3]);
        MMA_BF16(acc[1][1], A1l, B0h[1], B0h[3]);
        MMA_BF16(acc[1][1], A1h, B0l[1], B0l[3]);
        MMA_BF16(acc[1][2], A1h, B1h[0], B1h[2]);
        MMA_BF16(acc[1][2], A1l, B1h[0], B1h[2]);
        MMA_BF16(acc[1][2], A1h, B1l[0], B1l[2]);
        MMA_BF16(acc[1][3], A1h, B1h[1], B1h[3]);
        MMA_BF16(acc[1][3], A1l, B1h[1], B1h[3]);
        MMA_BF16(acc[1][3], A1h, B1l[1], B1l[3]);

        a0 += 32;   // k += 16 (bf16)
        w0 += 32;
    }
}

// ---------------------------------------------------------------------------
// persistent fused MLP: four fully independent 4-warp pipelines per CTA.
// Quadrant wm (0..3) owns rows wm*32..+32 of every 128-row tile; only
// named barrier wm+1 (128 threads) synchronizes inside the loop.
// ---------------------------------------------------------------------------
template <int GAMMA>
__global__ void __launch_bounds__(NTHREADS, 1)
mlp_kernel(const float* __restrict__ x, const int* __restrict__ seg,
           const float* __restrict__ b1g, const float* __restrict__ b2g,
           float* __restrict__ out, int nrows, int ntiles) {
    extern __shared__ char smp[];
    float* sb1 = (float*)(smp + B1_OFF);
    float* sb2 = (float*)(smp + B2_OFF);
    const uint32_t sbase = smem_u32(smp);

    const int tid  = threadIdx.x;
    const int lane = tid & 31, warp = tid >> 5;
    const int wm = warp >> 2, wn = warp & 3;    // quadrant wm, col-warp wn
    const int qtid = tid & 127;                 // thread within quadrant
    const int bid = wm + 1;                     // named barrier id
    const int rbase = wm * 32;

    int* qseg0 = (int*)(smp + SEG_OFF + wm * 256);
    int* qseg1 = qseg0 + 32;

    // ---- all 4 weight planes resident for CTA lifetime ----
    {
        const uint4* s = (const uint4*)(&g_Wp[GAMMA][0][0]);
        uint4* d = (uint4*)(smp + W_OFF);
        for (int i = tid; i < 4 * WPLANE / 16; i += NTHREADS) d[i] = s[i];
    }
    if (tid < 128) { sb1[tid] = b1g[tid]; sb2[tid] = b2g[tid]; }

    // ---- first tile: quadrant loads its own 32-row band ----
    int tile = blockIdx.x;
    {
        const int t0 = tile * 128;
#pragma unroll
        for (int j = 0; j < 8; ++j) {
            int i  = qtid + j * 128;
            int r  = rbase + (i >> 5);
            int c4 = (i & 31) * 4;
            float4 v = make_float4(0.f, 0.f, 0.f, 0.f);
            if (t0 + r < nrows)
                v = *(const float4*)(x + (size_t)(t0 + r) * 128 + c4);
            uint32_t h0, l0, h1, l1;
            split2(v.x, v.y, h0, l0);
            split2(v.z, v.w, h1, l1);
            *(uint2*)(smp + r * PITCH + c4 * 2)           = make_uint2(h0, h1);
            *(uint2*)(smp + A_L_OFF + r * PITCH + c4 * 2) = make_uint2(l0, l1);
        }
        if (qtid < 32)
            qseg0[qtid] = (t0 + rbase + qtid < nrows) ? seg[t0 + rbase + qtid] : -1;
    }
    __syncthreads();   // weights + biases + first bands visible

    const int gq = lane >> 2, t = lane & 3;
    // ldmatrix lane base addresses
    const int lr = lane & 7, lh = (lane >> 3) & 1, lk = lane >> 4;
    const uint32_t aBase  = sbase + (rbase + lr + lh * 8) * PITCH + lk * 16;
    const uint32_t wBase  = sbase + W_OFF + (wn * 32 + lr + lh * 8) * PITCH + lk * 16;
    const uint32_t wBase2 = wBase + 2 * WPLANE;

    int pb = 0;

    for (; tile < ntiles; tile += gridDim.x) {
        const int tile0 = tile * 128;
        int* scur = pb ? qseg1 : qseg0;
        int* snxt = pb ? qseg0 : qseg1;
        BARQ(bid);   // band X + seg visible; prev epilogue done

        // ---- prefetch next tile band into registers ----
        const int nxt = tile + gridDim.x;
        const bool hasnext = (nxt < ntiles);
        float4 pf[8];
        int psg = -1;
        if (hasnext) {
            const int n0 = nxt * 128;
#pragma unroll
            for (int j = 0; j < 8; ++j) {
                int i  = qtid + j * 128;
                int r  = rbase + (i >> 5);
                int c4 = (i & 31) * 4;
                pf[j] = (n0 + r < nrows)
                        ? *(const float4*)(x + (size_t)(n0 + r) * 128 + c4)
                        : make_float4(0.f, 0.f, 0.f, 0.f);
            }
            if (qtid < 32) psg = (n0 + rbase + qtid < nrows) ? seg[n0 + rbase + qtid] : -1;
        }

        // ================= stage 1: H = relu(X@W1 + b1) =================
        float acc[2][4][4];
#pragma unroll
        for (int a = 0; a < 2; ++a)
#pragma unroll
            for (int b = 0; b < 4; ++b)
#pragma unroll
                for (int c = 0; c < 4; ++c) acc[a][b][c] = 0.f;

        gemm_stage(aBase, wBase, acc);
        BARQ(bid);   // band X reads complete -> band free for H

#pragma unroll
        for (int mt = 0; mt < 2; ++mt)
#pragma unroll
            for (int nt = 0; nt < 4; ++nt) {
                int c = wn * 32 + nt * 8 + 2 * t;
                float bb0 = sb1[c], bb1 = sb1[c + 1];
                int r0 = rbase + mt * 16 + gq;
                float h0 = fmaxf(acc[mt][nt][0] + bb0, 0.f);
                float h1 = fmaxf(acc[mt][nt][1] + bb1, 0.f);
                float h2 = fmaxf(acc[mt][nt][2] + bb0, 0.f);
                float h3 = fmaxf(acc[mt][nt][3] + bb1, 0.f);
                uint32_t hi, lo;
                split2(h0, h1, hi, lo);
                *(uint32_t*)(smp + r0 * PITCH + c * 2)           = hi;
                *(uint32_t*)(smp + A_L_OFF + r0 * PITCH + c * 2) = lo;
                split2(h2, h3, hi, lo);
                *(uint32_t*)(smp + (r0 + 8) * PITCH + c * 2)           = hi;
                *(uint32_t*)(smp + A_L_OFF + (r0 + 8) * PITCH + c * 2) = lo;
            }
        BARQ(bid);   // H band ready

        // ================= stage 2: Y = H@W2 + b2 =================
#pragma unroll
        for (int a = 0; a < 2; ++a)
#pragma unroll
            for (int b = 0; b < 4; ++b)
#pragma unroll
                for (int c = 0; c < 4; ++c) acc[a][b][c] = 0.f;

        gemm_stage(aBase, wBase2, acc);
        BARQ(bid);   // H reads complete -> band free for next X

        // ---- store prefetched next-tile band ----
        if (hasnext) {
#pragma unroll
            for (int j = 0; j < 8; ++j) {
                int i  = qtid + j * 128;
                int r  = rbase + (i >> 5);
                int c4 = (i & 31) * 4;
                uint32_t h0, l0, h1, l1;
                split2(pf[j].x, pf[j].y, h0, l0);
                split2(pf[j].z, pf[j].w, h1, l1);
                *(uint2*)(smp + r * PITCH + c4 * 2)           = make_uint2(h0, h1);
                *(uint2*)(smp + A_L_OFF + r * PITCH + c4 * 2) = make_uint2(l0, l1);
            }
            if (qtid < 32) snxt[qtid] = psg;
        }

        // ================= epilogue (straight from accumulators) =================
        if (GAMMA) {
            int s0 = scur[0];
            bool uni = (s0 == scur[31]);
            if (uni && s0 >= 0) {
#pragma unroll
                for (int nt = 0; nt < 4; ++nt) {
                    float e0 = acc[0][nt][0] + acc[0][nt][2] + acc[1][nt][0] + acc[1][nt][2];
                    float e1 = acc[0][nt][1] + acc[0][nt][3] + acc[1][nt][1] + acc[1][nt][3];
#pragma unroll
                    for (int off = 4; off <= 16; off <<= 1) {
                        e0 += __shfl_xor_sync(0xffffffffu, e0, off);
                        e1 += __shfl_xor_sync(0xffffffffu, e1, off);
                    }
                    if (lane < 4) {
                        int c = wn * 32 + nt * 8 + 2 * lane;
                        atomicAdd(&g_psum[s0 * 128 + c],     e0 + 32.f * sb2[c]);
                        atomicAdd(&g_psum[s0 * 128 + c + 1], e1 + 32.f * sb2[c + 1]);
                    }
                }
            } else {
#pragma unroll
                for (int mt = 0; mt < 2; ++mt)
#pragma unroll
                    for (int h = 0; h < 2; ++h) {
                        int sl = mt * 16 + gq + h * 8;   // local row 0..31
                        int s = scur[sl];
                        if (s >= 0) {
#pragma unroll
                            for (int nt = 0; nt < 4; ++nt) {
                                int c = wn * 32 + nt * 8 + 2 * t;
                                atomicAdd(&g_psum[s * 128 + c],     acc[mt][nt][2 * h]     + sb2[c]);
                                atomicAdd(&g_psum[s * 128 + c + 1], acc[mt][nt][2 * h + 1] + sb2[c + 1]);
                            }
                        }
                    }
            }
            if (qtid == 0) {
                int cur = scur[0]; float run = 0.f;
                for (int r = 0; r < 32; ++r) {
                    int s = scur[r];
                    if (s != cur) {
                        if (cur >= 0) atomicAdd(&g_cnt[cur], run);
                        run = 0.f; cur = s;
                    }
                    run += 1.f;
                }
                if (cur >= 0) atomicAdd(&g_cnt[cur], run);
            }
        } else {
#pragma unroll
            for (int mt = 0; mt < 2; ++mt)
#pragma unroll
                for (int h = 0; h < 2; ++h) {
                    int sl = mt * 16 + gq + h * 8;       // local row
                    int rg = tile0 + rbase + sl;
                    if (rg < nrows) {
                        const float* pr = &g_pooled[scur[sl] * 128];
                        float* orow = out + (size_t)rg * 128;
#pragma unroll
                        for (int nt = 0; nt < 4; ++nt) {
                            int c = wn * 32 + nt * 8 + 2 * t;
                            float2 p = *(const float2*)(pr + c);
                            float2 o;
                            o.x = tanhf(acc[mt][nt][2 * h]     + sb2[c]     + p.x);
                            o.y = tanhf(acc[mt][nt][2 * h + 1] + sb2[c + 1] + p.y);
                            *(float2*)(orow + c) = o;
                        }
                    }
                }
        }
        pb ^= 1;
    }
}

// ---------------------------------------------------------------------------
extern "C" void kernel_launch(void* const* d_in, const int* in_sizes, int n_in,
                              void* d_out, int out_size) {
    const float* x    = (const float*)d_in[0];
    const int*   seg  = (const int*)d_in[1];
    const float* lW1  = (const float*)d_in[2];
    const float* lb1  = (const float*)d_in[3];
    const float* lW2  = (const float*)d_in[4];
    const float* lb2  = (const float*)d_in[5];
    const float* gW1  = (const float*)d_in[6];
    const float* gb1  = (const float*)d_in[7];
    const float* gW2  = (const float*)d_in[8];
    const float* gb2  = (const float*)d_in[9];

    int nrows  = in_sizes[0] / 128;
    int ntiles = (nrows + 127) / 128;

    int nsm = 148;
    cudaDeviceGetAttribute(&nsm, cudaDevAttrMultiProcessorCount, 0);
    if (nsm <= 0) nsm = 148;
    if (nsm > ntiles) nsm = ntiles;

    cudaFuncSetAttribute(mlp_kernel<1>, cudaFuncAttributeMaxDynamicSharedMemorySize, SMEM_BYTES);
    cudaFuncSetAttribute(mlp_kernel<0>, cudaFuncAttributeMaxDynamicSharedMemorySize, SMEM_BYTES);

    prep_kernel<<<128, 256>>>(lW1, lW2, gW1, gW2);
    mlp_kernel<1><<<nsm, NTHREADS, SMEM_BYTES>>>(x, seg, gb1, gb2, nullptr, nrows, ntiles);
    finalize_kernel<<<128, 256>>>();
    mlp_kernel<0><<<nsm, NTHREADS, SMEM_BYTES>>>(x, seg, lb1, lb2, (float*)d_out, nrows, ntiles);
}

// round 17
// speedup vs baseline: 1.7054x; 1.0169x over previous
#include <cuda_runtime.h>
#include <cuda_bf16.h>
#include <math.h>
#include <stdint.h>

#define S_SEG 256
#define NTHREADS 512   // 16 warps = 4 quadrants x 4 warps; quadrant owns 32 rows

// ---- smem layout (bytes). 128 bf16 cols = 256 B payload, PITCH 272 B ----
#define PITCH   272
#define WPLANE  34816                   // 128*272
#define A_L_OFF 34816                   // A: hi plane [0,34816), lo plane [34816,69632)
#define W_OFF   69632                   // W1H,W1L,W2H,W2L = 139264
#define B1_OFF  (W_OFF + 4 * WPLANE)    // 208896
#define B2_OFF  (B1_OFF + 512)          // 209408
#define SEG_OFF (B2_OFF + 512)          // 4 quadrants x 2 parity x 128 B
#define SMEM_BYTES (SEG_OFF + 1024)     // 210944

// global scratch: weight planes [branch][W1H,W1L,W2H,W2L][128*68 words]
__device__ uint32_t g_Wp[2][4][128 * 68];
__device__ float g_psum[S_SEG * 128];
__device__ float g_cnt[S_SEG];
__device__ float g_pooled[S_SEG * 128];

__device__ __forceinline__ uint32_t smem_u32(const void* p) {
    uint32_t a;
    asm("{ .reg .u64 t; cvta.to.shared.u64 t, %1; cvt.u32.u64 %0, t; }" : "=r"(a) : "l"(p));
    return a;
}

// hi = {bf16(b),bf16(a)}, lo = {bf16(b-hi.b),bf16(a-hi.a)} - 6 instructions
__device__ __forceinline__ void split2(float a, float b, uint32_t& hi, uint32_t& lo) {
    asm("cvt.rn.satfinite.bf16x2.f32 %0, %1, %2;" : "=r"(hi) : "f"(b), "f"(a));
    float af = __uint_as_float(hi << 16);
    float bf = __uint_as_float(hi & 0xffff0000u);
    float ar = a - af;
    float br = b - bf;
    asm("cvt.rn.satfinite.bf16x2.f32 %0, %1, %2;" : "=r"(lo) : "f"(br), "f"(ar));
}

#define MMA_BF16(d, a, b0v, b1v)                                              \
    asm volatile(                                                             \
        "mma.sync.aligned.m16n8k16.row.col.f32.bf16.bf16.f32 "                \
        "{%0,%1,%2,%3}, {%4,%5,%6,%7}, {%8,%9}, {%0,%1,%2,%3};"               \
        : "+f"((d)[0]), "+f"((d)[1]), "+f"((d)[2]), "+f"((d)[3])              \
        : "r"((a)[0]), "r"((a)[1]), "r"((a)[2]), "r"((a)[3]),                 \
          "r"(b0v), "r"(b1v))

#define LDSM4(r, addr)                                                        \
    asm volatile("ldmatrix.sync.aligned.m8n8.x4.shared.b16 {%0,%1,%2,%3}, [%4];" \
        : "=r"((r)[0]), "=r"((r)[1]), "=r"((r)[2]), "=r"((r)[3]) : "r"(addr))

// per-quadrant barrier: 4 consecutive warps = 128 threads, named barrier wm+1
#define BARQ(id)                                                              \
    asm volatile("bar.sync %0, 128;" :: "r"(id) : "memory")

#define TANH_APPROX(r, v)                                                     \
    asm("tanh.approx.f32 %0, %1;" : "=f"(r) : "f"(v))

// ---------------------------------------------------------------------------
__global__ void prep_kernel(const float* __restrict__ lW1, const float* __restrict__ lW2,
                            const float* __restrict__ gW1, const float* __restrict__ gW2) {
    int tid = blockIdx.x * blockDim.x + threadIdx.x;   // 0..32767
    if (tid < S_SEG * 128) g_psum[tid] = 0.f;
    if (tid < S_SEG)       g_cnt[tid]  = 0.f;
    int m   = tid >> 13;          // 0..3: lW1,lW2,gW1,gW2
    int idx = tid & 8191;
    int n   = idx & 127;
    int kp  = idx >> 7;           // 0..63
    const float* src = (m == 0) ? lW1 : (m == 1) ? lW2 : (m == 2) ? gW1 : gW2;
    int br = m >> 1;
    int ly = (m & 1) * 2;         // W1 -> planes 0,1 ; W2 -> planes 2,3
    float a = src[(2 * kp) * 128 + n];
    float b = src[(2 * kp + 1) * 128 + n];
    uint32_t hi, lo;
    split2(a, b, hi, lo);
    g_Wp[br][ly][n * 68 + kp]     = hi;
    g_Wp[br][ly + 1][n * 68 + kp] = lo;
}

__global__ void finalize_kernel() {
    int i = blockIdx.x * blockDim.x + threadIdx.x;
    if (i < S_SEG * 128)
        g_pooled[i] = g_psum[i] / fmaxf(g_cnt[i >> 7], 1.f);
}

// ---------------------------------------------------------------------------
// one GEMM stage: acc += 3-term split product (8 k-steps of 16).
// A hi plane at a0, lo at a0 + A_L_OFF; W hi plane at w0, lo at w0 + WPLANE.
// ---------------------------------------------------------------------------
__device__ __forceinline__ void gemm_stage(uint32_t a0, uint32_t w0, float (&acc)[2][4][4]) {
#pragma unroll
    for (int ks = 0; ks < 8; ++ks) {
        uint32_t A0h[4], A1h[4], A0l[4], A1l[4];
        LDSM4(A0h, a0);
        LDSM4(A1h, a0 + 16 * PITCH);
        LDSM4(A0l, a0 + A_L_OFF);
        LDSM4(A1l, a0 + A_L_OFF + 16 * PITCH);
        uint32_t B0h[4], B1h[4], B0l[4], B1l[4];
        LDSM4(B0h, w0);
        LDSM4(B1h, w0 + 16 * PITCH);
        LDSM4(B0l, w0 + WPLANE);
        LDSM4(B1l, w0 + WPLANE + 16 * PITCH);

        MMA_BF16(acc[0][0], A0h, B0h[0], B0h[2]);
        MMA_BF16(acc[0][0], A0l, B0h[0], B0h[2]);
        MMA_BF16(acc[0][0], A0h, B0l[0], B0l[2]);
        MMA_BF16(acc[0][1], A0h, B0h[1], B0h[3]);
        MMA_BF16(acc[0][1], A0l, B0h[1], B0h[3]);
        MMA_BF16(acc[0][1], A0h, B0l[1], B0l[3]);
        MMA_BF16(acc[0][2], A0h, B1h[0], B1h[2]);
        MMA_BF16(acc[0][2], A0l, B1h[0], B1h[2]);
        MMA_BF16(acc[0][2], A0h, B1l[0], B1l[2]);
        MMA_BF16(acc[0][3], A0h, B1h[1], B1h[3]);
        MMA_BF16(acc[0][3], A0l, B1h[1], B1h[3]);
        MMA_BF16(acc[0][3], A0h, B1l[1], B1l[3]);

        MMA_BF16(acc[1][0], A1h, B0h[0], B0h[2]);
        MMA_BF16(acc[1][0], A1l, B0h[0], B0h[2]);
        MMA_BF16(acc[1][0], A1h, B0l[0], B0l[2]);
        MMA_BF16(acc[1][1], A1h, B0h[1], B0h[3]);
        MMA_BF16(acc[1][1], A1l, B0h[1], B0h[3]);
        MMA_BF16(acc[1][1], A1h, B0l[1], B0l[3]);
        MMA_BF16(acc[1][2], A1h, B1h[0], B1h[2]);
        MMA_BF16(acc[1][2], A1l, B1h[0], B1h[2]);
        MMA_BF16(acc[1][2], A1h, B1l[0], B1l[2]);
        MMA_BF16(acc[1][3], A1h, B1h[1], B1h[3]);
        MMA_BF16(acc[1][3], A1l, B1h[1], B1h[3]);
        MMA_BF16(acc[1][3], A1h, B1l[1], B1l[3]);

        a0 += 32;   // k += 16 (bf16)
        w0 += 32;
    }
}

// ---------------------------------------------------------------------------
// persistent fused MLP: four independent 4-warp pipelines per CTA.
// Next-tile X is L2-prefetched at loop top (no register cost) and loaded
// (L2 hit) after gemm2, keeping regs free for k-loop pipelining.
// ---------------------------------------------------------------------------
template <int GAMMA>
__global__ void __launch_bounds__(NTHREADS, 1)
mlp_kernel(const float* __restrict__ x, const int* __restrict__ seg,
           const float* __restrict__ b1g, const float* __restrict__ b2g,
           float* __restrict__ out, int nrows, int ntiles) {
    extern __shared__ char smp[];
    float* sb1 = (float*)(smp + B1_OFF);
    float* sb2 = (float*)(smp + B2_OFF);
    const uint32_t sbase = smem_u32(smp);

    const int tid  = threadIdx.x;
    const int lane = tid & 31, warp = tid >> 5;
    const int wm = warp >> 2, wn = warp & 3;    // quadrant wm, col-warp wn
    const int qtid = tid & 127;                 // thread within quadrant
    const int bid = wm + 1;                     // named barrier id
    const int rbase = wm * 32;

    int* qseg0 = (int*)(smp + SEG_OFF + wm * 256);
    int* qseg1 = qseg0 + 32;

    // ---- all 4 weight planes resident for CTA lifetime ----
    {
        const uint4* s = (const uint4*)(&g_Wp[GAMMA][0][0]);
        uint4* d = (uint4*)(smp + W_OFF);
        for (int i = tid; i < 4 * WPLANE / 16; i += NTHREADS) d[i] = s[i];
    }
    if (tid < 128) { sb1[tid] = b1g[tid]; sb2[tid] = b2g[tid]; }

    // ---- first tile: quadrant loads its own 32-row band ----
    int tile = blockIdx.x;
    {
        const int t0 = tile * 128;
#pragma unroll
        for (int j = 0; j < 8; ++j) {
            int i  = qtid + j * 128;
            int r  = rbase + (i >> 5);
            int c4 = (i & 31) * 4;
            float4 v = make_float4(0.f, 0.f, 0.f, 0.f);
            if (t0 + r < nrows)
                v = *(const float4*)(x + (size_t)(t0 + r) * 128 + c4);
            uint32_t h0, l0, h1, l1;
            split2(v.x, v.y, h0, l0);
            split2(v.z, v.w, h1, l1);
            *(uint2*)(smp + r * PITCH + c4 * 2)           = make_uint2(h0, h1);
            *(uint2*)(smp + A_L_OFF + r * PITCH + c4 * 2) = make_uint2(l0, l1);
        }
        if (qtid < 32)
            qseg0[qtid] = (t0 + rbase + qtid < nrows) ? seg[t0 + rbase + qtid] : -1;
    }
    __syncthreads();   // weights + biases + first bands visible

    const int gq = lane >> 2, t = lane & 3;
    // ldmatrix lane base addresses
    const int lr = lane & 7, lh = (lane >> 3) & 1, lk = lane >> 4;
    const uint32_t aBase  = sbase + (rbase + lr + lh * 8) * PITCH + lk * 16;
    const uint32_t wBase  = sbase + W_OFF + (wn * 32 + lr + lh * 8) * PITCH + lk * 16;
    const uint32_t wBase2 = wBase + 2 * WPLANE;

    int pb = 0;

    for (; tile < ntiles; tile += gridDim.x) {
        const int tile0 = tile * 128;
        int* scur = pb ? qseg1 : qseg0;
        int* snxt = pb ? qseg0 : qseg1;
        BARQ(bid);   // band X + seg visible; prev epilogue done

        const int nxt = tile + gridDim.x;
        const bool hasnext = (nxt < ntiles);

        // ---- L2 prefetch of next tile band (no register cost) ----
        if (hasnext && (lane & 7) == 0) {
            const int n0 = nxt * 128;
#pragma unroll
            for (int j = 0; j < 8; ++j) {
                int i  = qtid + j * 128;
                int r  = rbase + (i >> 5);
                int c4 = (i & 31) * 4;    // lanes 0,8,16,24 -> one 128B line each
                if (n0 + r < nrows)
                    asm volatile("prefetch.global.L2 [%0];"
                                 :: "l"(x + (size_t)(n0 + r) * 128 + c4) : "memory");
            }
        }

        // ================= stage 1: H = relu(X@W1 + b1) =================
        float acc[2][4][4];
#pragma unroll
        for (int a = 0; a < 2; ++a)
#pragma unroll
            for (int b = 0; b < 4; ++b)
#pragma unroll
                for (int c = 0; c < 4; ++c) acc[a][b][c] = 0.f;

        gemm_stage(aBase, wBase, acc);
        BARQ(bid);   // band X reads complete -> band free for H

#pragma unroll
        for (int mt = 0; mt < 2; ++mt)
#pragma unroll
            for (int nt = 0; nt < 4; ++nt) {
                int c = wn * 32 + nt * 8 + 2 * t;
                float bb0 = sb1[c], bb1 = sb1[c + 1];
                int r0 = rbase + mt * 16 + gq;
                float h0 = fmaxf(acc[mt][nt][0] + bb0, 0.f);
                float h1 = fmaxf(acc[mt][nt][1] + bb1, 0.f);
                float h2 = fmaxf(acc[mt][nt][2] + bb0, 0.f);
                float h3 = fmaxf(acc[mt][nt][3] + bb1, 0.f);
                uint32_t hi, lo;
                split2(h0, h1, hi, lo);
                *(uint32_t*)(smp + r0 * PITCH + c * 2)           = hi;
                *(uint32_t*)(smp + A_L_OFF + r0 * PITCH + c * 2) = lo;
                split2(h2, h3, hi, lo);
                *(uint32_t*)(smp + (r0 + 8) * PITCH + c * 2)           = hi;
                *(uint32_t*)(smp + A_L_OFF + (r0 + 8) * PITCH + c * 2) = lo;
            }
        BARQ(bid);   // H band ready

        // ================= stage 2: Y = H@W2 + b2 =================
#pragma unroll
        for (int a = 0; a < 2; ++a)
#pragma unroll
            for (int b = 0; b < 4; ++b)
#pragma unroll
                for (int c = 0; c < 4; ++c) acc[a][b][c] = 0.f;

        gemm_stage(aBase, wBase2, acc);
        BARQ(bid);   // H reads complete -> band free for next X

        // ---- load next-tile band (L2 hit), split, store ----
        if (hasnext) {
            const int n0 = nxt * 128;
#pragma unroll
            for (int j = 0; j < 8; ++j) {
                int i  = qtid + j * 128;
                int r  = rbase + (i >> 5);
                int c4 = (i & 31) * 4;
                float4 v = make_float4(0.f, 0.f, 0.f, 0.f);
                if (n0 + r < nrows)
                    v = *(const float4*)(x + (size_t)(n0 + r) * 128 + c4);
                uint32_t h0, l0, h1, l1;
                split2(v.x, v.y, h0, l0);
                split2(v.z, v.w, h1, l1);
                *(uint2*)(smp + r * PITCH + c4 * 2)           = make_uint2(h0, h1);
                *(uint2*)(smp + A_L_OFF + r * PITCH + c4 * 2) = make_uint2(l0, l1);
            }
            if (qtid < 32)
                snxt[qtid] = (n0 + rbase + qtid < nrows) ? seg[n0 + rbase + qtid] : -1;
        }

        // ================= epilogue (straight from accumulators) =================
        if (GAMMA) {
            int s0 = scur[0];
            bool uni = (s0 == scur[31]);
            if (uni && s0 >= 0) {
#pragma unroll
                for (int nt = 0; nt < 4; ++nt) {
                    float e0 = acc[0][nt][0] + acc[0][nt][2] + acc[1][nt][0] + acc[1][nt][2];
                    float e1 = acc[0][nt][1] + acc[0][nt][3] + acc[1][nt][1] + acc[1][nt][3];
#pragma unroll
                    for (int off = 4; off <= 16; off <<= 1) {
                        e0 += __shfl_xor_sync(0xffffffffu, e0, off);
                        e1 += __shfl_xor_sync(0xffffffffu, e1, off);
                    }
                    if (lane < 4) {
                        int c = wn * 32 + nt * 8 + 2 * lane;
                        atomicAdd(&g_psum[s0 * 128 + c],     e0 + 32.f * sb2[c]);
                        atomicAdd(&g_psum[s0 * 128 + c + 1], e1 + 32.f * sb2[c + 1]);
                    }
                }
            } else {
#pragma unroll
                for (int mt = 0; mt < 2; ++mt)
#pragma unroll
                    for (int h = 0; h < 2; ++h) {
                        int sl = mt * 16 + gq + h * 8;   // local row 0..31
                        int s = scur[sl];
                        if (s >= 0) {
#pragma unroll
                            for (int nt = 0; nt < 4; ++nt) {
                                int c = wn * 32 + nt * 8 + 2 * t;
                                atomicAdd(&g_psum[s * 128 + c],     acc[mt][nt][2 * h]     + sb2[c]);
                                atomicAdd(&g_psum[s * 128 + c + 1], acc[mt][nt][2 * h + 1] + sb2[c + 1]);
                            }
                        }
                    }
            }
            if (qtid == 0) {
                int cur = scur[0]; float run = 0.f;
                for (int r = 0; r < 32; ++r) {
                    int s = scur[r];
                    if (s != cur) {
                        if (cur >= 0) atomicAdd(&g_cnt[cur], run);
                        run = 0.f; cur = s;
                    }
                    run += 1.f;
                }
                if (cur >= 0) atomicAdd(&g_cnt[cur], run);
            }
        } else {
#pragma unroll
            for (int mt = 0; mt < 2; ++mt)
#pragma unroll
                for (int h = 0; h < 2; ++h) {
                    int sl = mt * 16 + gq + h * 8;       // local row
                    int rg = tile0 + rbase + sl;
                    if (rg < nrows) {
                        const float* pr = &g_pooled[scur[sl] * 128];
                        float* orow = out + (size_t)rg * 128;
#pragma unroll
                        for (int nt = 0; nt < 4; ++nt) {
                            int c = wn * 32 + nt * 8 + 2 * t;
                            float2 p = *(const float2*)(pr + c);
                            float2 o;
                            TANH_APPROX(o.x, acc[mt][nt][2 * h]     + sb2[c]     + p.x);
                            TANH_APPROX(o.y, acc[mt][nt][2 * h + 1] + sb2[c + 1] + p.y);
                            *(float2*)(orow + c) = o;
                        }
                    }
                }
        }
        pb ^= 1;
    }
}

// ---------------------------------------------------------------------------
extern "C" void kernel_launch(void* const* d_in, const int* in_sizes, int n_in,
                              void* d_out, int out_size) {
    const float* x    = (const float*)d_in[0];
    const int*   seg  = (const int*)d_in[1];
    const float* lW1  = (const float*)d_in[2];
    const float* lb1  = (const float*)d_in[3];
    const float* lW2  = (const float*)d_in[4];
    const float* lb2  = (const float*)d_in[5];
    const float* gW1  = (const float*)d_in[6];
    const float* gb1  = (const float*)d_in[7];
    const float* gW2  = (const float*)d_in[8];
    const float* gb2  = (const float*)d_in[9];

    int nrows  = in_sizes[0] / 128;
    int ntiles = (nrows + 127) / 128;

    int nsm = 148;
    cudaDeviceGetAttribute(&nsm, cudaDevAttrMultiProcessorCount, 0);
    if (nsm <= 0) nsm = 148;
    if (nsm > ntiles) nsm = ntiles;

    cudaFuncSetAttribute(mlp_kernel<1>, cudaFuncAttributeMaxDynamicSharedMemorySize, SMEM_BYTES);
    cudaFuncSetAttribute(mlp_kernel<0>, cudaFuncAttributeMaxDynamicSharedMemorySize, SMEM_BYTES);

    prep_kernel<<<128, 256>>>(lW1, lW2, gW1, gW2);
    mlp_kernel<1><<<nsm, NTHREADS, SMEM_BYTES>>>(x, seg, gb1, gb2, nullptr, nrows, ntiles);
    finalize_kernel<<<128, 256>>>();
    mlp_kernel<0><<<nsm, NTHREADS, SMEM_BYTES>>>(x, seg, lb1, lb2, (float*)d_out, nrows, ntiles);
}